// round 6
// baseline (speedup 1.0000x reference)
#include <cuda_runtime.h>
#include <cuda_bf16.h>
#include <math.h>
#include <stdint.h>

// ---------------- problem constants ----------------
#define B_IMG   16
#define C_CH    256
#define HID_CH  1024
#define HW      3136
#define W_DIM   56
#define PER_B   (C_CH * HW)
#define NPIX    (B_IMG * HW)          // 50176
#define NBLK_RED 128
#define SEG_RED (PER_B / NBLK_RED)    // 6272

// GEMM tile config: 3-stage pipeline, 64B swizzled rows
#define BM 128
#define BN 128
#define BK 32
#define ROW_B   64                     // bytes per tile row (32 bf16)
#define TBUF_B  (BM * ROW_B)           // 8192 per buffer
#define STAGE_B (4 * TBUF_B)           // A_hi A_lo B_hi B_lo = 32768
#define OFF_A_HI(s) ((s) * STAGE_B)
#define OFF_A_LO(s) ((s) * STAGE_B + TBUF_B)
#define OFF_B_HI(s) ((s) * STAGE_B + 2 * TBUF_B)
#define OFF_B_LO(s) ((s) * STAGE_B + 3 * TBUF_B)
#define NSTAGE  3
#define SMEM_BYTES (NSTAGE * STAGE_B)  // 98304
#define EP_STRIDE 132

// ---------------- scratch ----------------
__device__ float g_bufA[B_IMG * C_CH * HW];
__device__ float g_bufS[B_IMG * C_CH * HW];
__device__ float g_bufX1[B_IMG * C_CH * HW];
__device__ unsigned g_bufHID[B_IMG * HID_CH * HW];   // packed hi|lo<<16
__device__ unsigned g_tpack[B_IMG * C_CH * HW];      // packed t = gelu(GN(bufA))
__device__ float2 g_part[B_IMG * NBLK_RED];
__device__ float2 g_stats[4 * B_IMG];
#define WTOT (4*C_CH*C_CH + 2*HID_CH*C_CH)
__device__ __nv_bfloat16 g_wh[WTOT];
__device__ __nv_bfloat16 g_wl[WTOT];

__device__ __forceinline__ float gelu_f(float v) {
    return 0.5f * v * (1.0f + erff(v * 0.7071067811865476f));
}
__device__ __forceinline__ unsigned pack_split(float v) {
    __nv_bfloat16 h = __float2bfloat16(v);
    __nv_bfloat16 l = __float2bfloat16(v - __bfloat162float(h));
    return (unsigned)__bfloat16_as_ushort(h) | ((unsigned)__bfloat16_as_ushort(l) << 16);
}
__device__ __forceinline__ unsigned smem_u32(const void* p) {
    unsigned a;
    asm("{ .reg .u64 t; cvta.to.shared.u64 t, %1; cvt.u32.u64 %0, t; }" : "=r"(a) : "l"(p));
    return a;
}
// 64B-row swizzle: 16B slot q XOR'd by (row>>1)&3  -> conflict-free ldmatrix phases
__device__ __forceinline__ unsigned swz(unsigned row, unsigned bofs) {
    return row * ROW_B + ((((bofs >> 4) ^ ((row >> 1) & 3)) << 4) | (bofs & 15));
}
#define LDSM_X4(r, addr) \
    asm volatile("ldmatrix.sync.aligned.m8n8.x4.shared.b16 {%0,%1,%2,%3}, [%4];" \
                 : "=r"((r)[0]), "=r"((r)[1]), "=r"((r)[2]), "=r"((r)[3]) : "r"(addr))
#define MMA_BF16(d, a, b0, b1) \
    asm volatile("mma.sync.aligned.m16n8k16.row.col.f32.bf16.bf16.f32 " \
                 "{%0,%1,%2,%3}, {%4,%5,%6,%7}, {%8,%9}, {%0,%1,%2,%3};" \
                 : "+f"((d)[0]), "+f"((d)[1]), "+f"((d)[2]), "+f"((d)[3]) \
                 : "r"((a)[0]), "r"((a)[1]), "r"((a)[2]), "r"((a)[3]), "r"(b0), "r"(b1))
#define CP_ASYNC16(saddr, gptr) \
    asm volatile("cp.async.cg.shared.global [%0], [%1], 16;" :: "r"(saddr), "l"(gptr) : "memory")
#define CP_COMMIT() asm volatile("cp.async.commit_group;" ::: "memory")
#define CP_WAIT0()  asm volatile("cp.async.wait_group 0;" ::: "memory")
#define CP_WAIT1()  asm volatile("cp.async.wait_group 1;" ::: "memory")

// ---------------- GN reductions ----------------
__global__ void reduce_part_k(const float* __restrict__ src, float2* __restrict__ part) {
    int b = blockIdx.x, blk = blockIdx.y;
    const float4* p = (const float4*)(src + (size_t)b * PER_B + blk * SEG_RED);
    float s = 0.f, ss = 0.f;
    for (int i = threadIdx.x; i < SEG_RED / 4; i += 256) {
        float4 v = p[i];
        s  += v.x + v.y + v.z + v.w;
        ss += v.x*v.x + v.y*v.y + v.z*v.z + v.w*v.w;
    }
    __shared__ float sh1[256], sh2[256];
    int t = threadIdx.x;
    sh1[t] = s; sh2[t] = ss;
    __syncthreads();
    for (int st = 128; st > 0; st >>= 1) {
        if (t < st) { sh1[t] += sh1[t+st]; sh2[t] += sh2[t+st]; }
        __syncthreads();
    }
    if (t == 0) part[b * NBLK_RED + blk] = make_float2(sh1[0], sh2[0]);
}

__global__ void finalize_k(const float2* __restrict__ part, float2* __restrict__ stats) {
    int b = threadIdx.x;
    if (b >= B_IMG) return;
    float s = 0.f, ss = 0.f;
    for (int i = 0; i < NBLK_RED; i++) {
        float2 p = part[b * NBLK_RED + i];
        s += p.x; ss += p.y;
    }
    const float n = (float)PER_B;
    float mean = s / n;
    float var  = ss / n - mean * mean;
    stats[b] = make_float2(mean, rsqrtf(var + 1e-5f));
}

// ---------------- all 6 weight splits in ONE launch ----------------
__global__ void wsplit_all_k(const float* s0, const float* s1, const float* s2,
                             const float* s3, const float* s4, const float* s5,
                             __nv_bfloat16* __restrict__ wh, __nv_bfloat16* __restrict__ wl) {
    const int NWS = C_CH * C_CH, NWB = HID_CH * C_CH;
    const float* srcs[6] = { s0, s1, s2, s3, s4, s5 };
    const int offs[6] = { 0, NWS, 2*NWS, 3*NWS, 4*NWS, 4*NWS + NWB };
    const int ns[6]   = { NWS, NWS, NWS, NWS, NWB, NWB };
    int g = blockIdx.y;
    int i = blockIdx.x * 256 + threadIdx.x;
    if (i < ns[g]) {
        float x = srcs[g][i];
        __nv_bfloat16 h = __float2bfloat16(x);
        wh[offs[g] + i] = h;
        wl[offs[g] + i] = __float2bfloat16(x - __bfloat162float(h));
    }
}

// ---------------- tpass: t = gelu(GN(bufA)) -> packed u32 ----------------
__global__ void tpass_k(const float* __restrict__ src, const float2* __restrict__ stats,
                        const float* __restrict__ gamma, const float* __restrict__ beta,
                        unsigned* __restrict__ dst) {
    int i4 = blockIdx.x * 256 + threadIdx.x;
    const int total4 = B_IMG * C_CH * HW / 4;
    if (i4 >= total4) return;
    int i = i4 * 4;
    int b = i / PER_B;
    int r = i - b * PER_B;
    int c = r / HW;
    float2 st = stats[b];
    float g = gamma[c], be = beta[c];
    float4 v = ((const float4*)src)[i4];
    uint4 o;
    o.x = pack_split(gelu_f((v.x - st.x) * st.y * g + be));
    o.y = pack_split(gelu_f((v.y - st.x) * st.y * g + be));
    o.z = pack_split(gelu_f((v.z - st.x) * st.y * g + be));
    o.w = pack_split(gelu_f((v.w - st.x) * st.y * g + be));
    ((uint4*)dst)[i4] = o;
}

// ---------------- fused HMMA GEMM ----------------
#define IN_GN        0
#define IN_PACKED    1
#define IN_PSHIFT_W  2
#define IN_PSHIFT_H  3
#define OUT_RAW       0
#define OUT_GELU      1
#define OUT_GELU_ACC  2
#define OUT_ADD_RES   3
#define OUT_GELU_PACK 4

template<int IM>
__device__ __forceinline__ unsigned load_u(const void* __restrict__ Bsrc, int K, int b_img,
                                           int hw, int hh, int ww, float mean, float rstd,
                                           const float* __restrict__ gamma,
                                           const float* __restrict__ beta, int c, int group) {
    if (IM == IN_GN) {
        float v = ((const float*)Bsrc)[((size_t)b_img * K + c) * HW + hw];
        return __float_as_uint((v - mean) * rstd * gamma[c] + beta[c]);
    } else if (IM == IN_PACKED) {
        return ((const unsigned*)Bsrc)[((size_t)b_img * K + c) * HW + hw];
    } else if (IM == IN_PSHIFT_W) {
        int s = 3 - c / group;
        int w2 = ww + s;
        if (w2 < 0 || w2 >= W_DIM) return 0u;
        return ((const unsigned*)Bsrc)[((size_t)b_img * K + c) * HW + hh * W_DIM + w2];
    } else {
        int s = 3 - c / group;
        int h2 = hh + s;
        if (h2 < 0 || h2 >= W_DIM) return 0u;
        return ((const unsigned*)Bsrc)[((size_t)b_img * K + c) * HW + h2 * W_DIM + ww];
    }
}

template<int IM>
__device__ __forceinline__ void sts_pair(unsigned ah, unsigned al, int px, int cpair,
                                         unsigned a0, unsigned a1) {
    unsigned hp, lp;
    if (IM == IN_GN) {
        float v0 = __uint_as_float(a0), v1 = __uint_as_float(a1);
        __nv_bfloat16 h0 = __float2bfloat16(v0);
        __nv_bfloat16 h1 = __float2bfloat16(v1);
        __nv_bfloat16 l0 = __float2bfloat16(v0 - __bfloat162float(h0));
        __nv_bfloat16 l1 = __float2bfloat16(v1 - __bfloat162float(h1));
        hp = (unsigned)__bfloat16_as_ushort(h0) | ((unsigned)__bfloat16_as_ushort(h1) << 16);
        lp = (unsigned)__bfloat16_as_ushort(l0) | ((unsigned)__bfloat16_as_ushort(l1) << 16);
    } else {
        hp = __byte_perm(a0, a1, 0x5410);
        lp = __byte_perm(a0, a1, 0x7632);
    }
    unsigned off = swz((unsigned)px, (unsigned)cpair * 4);
    asm volatile("st.shared.b32 [%0], %1;" :: "r"(ah + off), "r"(hp) : "memory");
    asm volatile("st.shared.b32 [%0], %1;" :: "r"(al + off), "r"(lp) : "memory");
}

template<int IM, int OM>
__global__ void __launch_bounds__(256, 2) mma_gemm_k(
    const __nv_bfloat16* __restrict__ Wh, const __nv_bfloat16* __restrict__ Wl,
    const void* __restrict__ Bsrc, const float* __restrict__ bias,
    const float2* __restrict__ stats, const float* __restrict__ gamma,
    const float* __restrict__ beta, const float* __restrict__ res,
    void* __restrict__ out, int Mout, int K)
{
    extern __shared__ char smem[];
    const unsigned sbase = smem_u32(smem);

    const int tid  = threadIdx.x;
    const int wid  = tid >> 5;
    const int lane = tid & 31;
    const int warp_m = wid & 3;
    const int warp_n = wid >> 2;

    const int px   = tid & 127;
    const int hseg = tid >> 7;
    const int gpix = blockIdx.x * BM + px;
    const int b_img = gpix / HW;
    const int hw    = gpix - b_img * HW;
    const int hh    = hw / W_DIM;
    const int ww    = hw - hh * W_DIM;
    float mean = 0.f, rstd = 0.f;
    if (IM == IN_GN) { float2 st = stats[b_img]; mean = st.x; rstd = st.y; }
    const int group = (K + 6) / 7;
    const int n0 = blockIdx.y * BN;
    const int nch = K / BK;

    const int brow0 = tid >> 2;
    const int bq0   = tid & 3;
    const int brow1 = (tid + 256) >> 2;
    const int bq1   = (tid + 256) & 3;
    const unsigned bs0 = swz((unsigned)brow0, (unsigned)bq0 * 16);
    const unsigned bs1 = swz((unsigned)brow1, (unsigned)bq1 * 16);

    float acc[2][8][4];
    #pragma unroll
    for (int i = 0; i < 2; i++)
        #pragma unroll
        for (int j = 0; j < 8; j++)
            #pragma unroll
            for (int q = 0; q < 4; q++) acc[i][j][q] = 0.f;

    unsigned areg[16];

    // ---- prologue: stage chunks 0 and 1 ----
    #pragma unroll
    for (int s = 0; s < 2; ++s) {
        const int kk = s * BK;
        unsigned bh = sbase + OFF_B_HI(s), bl = sbase + OFF_B_LO(s);
        CP_ASYNC16(bh + bs0, Wh + (size_t)(n0 + brow0) * K + kk + bq0 * 8);
        CP_ASYNC16(bh + bs1, Wh + (size_t)(n0 + brow1) * K + kk + bq1 * 8);
        CP_ASYNC16(bl + bs0, Wl + (size_t)(n0 + brow0) * K + kk + bq0 * 8);
        CP_ASYNC16(bl + bs1, Wl + (size_t)(n0 + brow1) * K + kk + bq1 * 8);
        CP_COMMIT();
        #pragma unroll
        for (int j = 0; j < 16; j++)
            areg[j] = load_u<IM>(Bsrc, K, b_img, hw, hh, ww, mean, rstd, gamma, beta,
                                 kk + hseg * 16 + j, group);
        unsigned ah = sbase + OFF_A_HI(s), al = sbase + OFF_A_LO(s);
        #pragma unroll
        for (int j = 0; j < 16; j += 2)
            sts_pair<IM>(ah, al, px, hseg * 8 + (j >> 1), areg[j], areg[j+1]);
    }
    CP_WAIT1();
    __syncthreads();

    const unsigned a_lrow = warp_m * 32 + (lane & 15);
    const unsigned a_lcol = (lane >> 4) * 16;
    const unsigned b_lrow = warp_n * 64 + ((lane & 16) >> 1) + (lane & 7);
    const unsigned b_lcol = ((lane >> 3) & 1) * 16;

    int stage = 0;
    for (int i = 0; i < nch; ++i) {
        const bool pre = (i + 2 < nch);
        const int sN = (stage + 2 >= NSTAGE) ? stage + 2 - NSTAGE : stage + 2;
        if (pre) {
            const int kk = (i + 2) * BK;
            unsigned bh = sbase + OFF_B_HI(sN), bl = sbase + OFF_B_LO(sN);
            CP_ASYNC16(bh + bs0, Wh + (size_t)(n0 + brow0) * K + kk + bq0 * 8);
            CP_ASYNC16(bh + bs1, Wh + (size_t)(n0 + brow1) * K + kk + bq1 * 8);
            CP_ASYNC16(bl + bs0, Wl + (size_t)(n0 + brow0) * K + kk + bq0 * 8);
            CP_ASYNC16(bl + bs1, Wl + (size_t)(n0 + brow1) * K + kk + bq1 * 8);
            CP_COMMIT();
            #pragma unroll
            for (int j = 0; j < 16; j++)
                areg[j] = load_u<IM>(Bsrc, K, b_img, hw, hh, ww, mean, rstd, gamma, beta,
                                     kk + hseg * 16 + j, group);
        }

        // ---- compute chunk i from stage ----
        const unsigned Ah = sbase + OFF_A_HI(stage), Al = sbase + OFF_A_LO(stage);
        const unsigned Bh = sbase + OFF_B_HI(stage), Bl = sbase + OFF_B_LO(stage);
        #pragma unroll
        for (int ks = 0; ks < 2; ++ks) {
            unsigned ahf[2][4], alf[2][4];
            #pragma unroll
            for (int mi = 0; mi < 2; ++mi) {
                unsigned row = a_lrow + mi * 16;
                unsigned off = swz(row, ks * 32 + a_lcol);
                LDSM_X4(ahf[mi], Ah + off);
                LDSM_X4(alf[mi], Al + off);
            }
            #pragma unroll
            for (int nip = 0; nip < 4; ++nip) {
                unsigned bhf[4], blf[4];
                unsigned row = b_lrow + nip * 16;
                unsigned off = swz(row, ks * 32 + b_lcol);
                LDSM_X4(bhf, Bh + off);
                LDSM_X4(blf, Bl + off);
                #pragma unroll
                for (int mi = 0; mi < 2; ++mi) {
                    #pragma unroll
                    for (int h = 0; h < 2; ++h) {
                        float* d = acc[mi][nip * 2 + h];
                        MMA_BF16(d, ahf[mi], bhf[2*h], bhf[2*h+1]);
                        MMA_BF16(d, ahf[mi], blf[2*h], blf[2*h+1]);
                        MMA_BF16(d, alf[mi], bhf[2*h], bhf[2*h+1]);
                    }
                }
            }
        }

        if (pre) {
            unsigned ah = sbase + OFF_A_HI(sN), al = sbase + OFF_A_LO(sN);
            #pragma unroll
            for (int j = 0; j < 16; j += 2)
                sts_pair<IM>(ah, al, px, hseg * 8 + (j >> 1), areg[j], areg[j+1]);
            CP_WAIT1();
        } else {
            CP_WAIT0();
        }
        __syncthreads();
        stage = (stage + 1 >= NSTAGE) ? 0 : stage + 1;
    }

    // ---- epilogue via smem transpose (aliases tile smem) ----
    float* ep = (float*)smem;
    const int r4 = lane >> 2;
    const int c2 = (lane & 3) * 2;
    #pragma unroll
    for (int mi = 0; mi < 2; ++mi) {
        #pragma unroll
        for (int ni = 0; ni < 8; ++ni) {
            int m = warp_m * 32 + mi * 16 + r4;
            int n = warp_n * 64 + ni * 8 + c2;
            ep[n * EP_STRIDE + m]           = acc[mi][ni][0];
            ep[(n + 1) * EP_STRIDE + m]     = acc[mi][ni][1];
            ep[n * EP_STRIDE + m + 8]       = acc[mi][ni][2];
            ep[(n + 1) * EP_STRIDE + m + 8] = acc[mi][ni][3];
        }
    }
    __syncthreads();

    #pragma unroll 4
    for (int it = 0; it < 64; ++it) {
        int flat = it * 256 + tid;
        int nl = flat >> 7;
        int m  = flat & 127;
        int g  = blockIdx.x * BM + m;
        int be = g / HW;
        int hwe = g - be * HW;
        int n  = n0 + nl;
        float v = ep[nl * EP_STRIDE + m] + bias[n];
        size_t idx = ((size_t)be * Mout + n) * HW + hwe;
        if (OM == OUT_RAW)            ((float*)out)[idx] = v;
        else if (OM == OUT_GELU)      ((float*)out)[idx] = gelu_f(v);
        else if (OM == OUT_GELU_ACC)  ((float*)out)[idx] += gelu_f(v);
        else if (OM == OUT_ADD_RES)   ((float*)out)[idx] = v + res[idx];
        else                          ((unsigned*)out)[idx] = pack_split(gelu_f(v));
    }
}

// ---------------- launch ----------------
extern "C" void kernel_launch(void* const* d_in, const int* in_sizes, int n_in,
                              void* d_out, int out_size)
{
    const float* x      = (const float*)d_in[0];
    const float* n1_w   = (const float*)d_in[1];
    const float* n1_b   = (const float*)d_in[2];
    const float* c1_w   = (const float*)d_in[3];
    const float* c1_b   = (const float*)d_in[4];
    const float* asn1_w = (const float*)d_in[5];
    const float* asn1_b = (const float*)d_in[6];
    const float* c21_w  = (const float*)d_in[7];
    const float* c21_b  = (const float*)d_in[8];
    const float* c22_w  = (const float*)d_in[9];
    const float* c22_b  = (const float*)d_in[10];
    const float* asn2_w = (const float*)d_in[11];
    const float* asn2_b = (const float*)d_in[12];
    const float* c3_w   = (const float*)d_in[13];
    const float* c3_b   = (const float*)d_in[14];
    const float* n2_w   = (const float*)d_in[15];
    const float* n2_b   = (const float*)d_in[16];
    const float* fc1_w  = (const float*)d_in[17];
    const float* fc1_b  = (const float*)d_in[18];
    const float* fc2_w  = (const float*)d_in[19];
    const float* fc2_b  = (const float*)d_in[20];
    float* out = (float*)d_out;

    float *bufA, *bufS, *bufX1;
    unsigned *bufHID, *tpack;
    float2 *part, *stats;
    __nv_bfloat16 *wh, *wl;
    cudaGetSymbolAddress((void**)&bufA,   g_bufA);
    cudaGetSymbolAddress((void**)&bufS,   g_bufS);
    cudaGetSymbolAddress((void**)&bufX1,  g_bufX1);
    cudaGetSymbolAddress((void**)&bufHID, g_bufHID);
    cudaGetSymbolAddress((void**)&tpack,  g_tpack);
    cudaGetSymbolAddress((void**)&part,   g_part);
    cudaGetSymbolAddress((void**)&stats,  g_stats);
    cudaGetSymbolAddress((void**)&wh,     g_wh);
    cudaGetSymbolAddress((void**)&wl,     g_wl);

    float2* st0 = stats + 0 * B_IMG;
    float2* st1 = stats + 1 * B_IMG;
    float2* st2 = stats + 2 * B_IMG;
    float2* st3 = stats + 3 * B_IMG;

    const int NWS = C_CH * C_CH, NWB = HID_CH * C_CH;
    const int O_C1 = 0, O_C21 = NWS, O_C22 = 2*NWS, O_C3 = 3*NWS,
              O_FC1 = 4*NWS, O_FC2 = 4*NWS + NWB;

    cudaFuncSetAttribute(mma_gemm_k<IN_GN,       OUT_RAW>,       cudaFuncAttributeMaxDynamicSharedMemorySize, SMEM_BYTES);
    cudaFuncSetAttribute(mma_gemm_k<IN_PSHIFT_W, OUT_GELU>,      cudaFuncAttributeMaxDynamicSharedMemorySize, SMEM_BYTES);
    cudaFuncSetAttribute(mma_gemm_k<IN_PSHIFT_H, OUT_GELU_ACC>,  cudaFuncAttributeMaxDynamicSharedMemorySize, SMEM_BYTES);
    cudaFuncSetAttribute(mma_gemm_k<IN_GN,       OUT_ADD_RES>,   cudaFuncAttributeMaxDynamicSharedMemorySize, SMEM_BYTES);
    cudaFuncSetAttribute(mma_gemm_k<IN_GN,       OUT_GELU_PACK>, cudaFuncAttributeMaxDynamicSharedMemorySize, SMEM_BYTES);
    cudaFuncSetAttribute(mma_gemm_k<IN_PACKED,   OUT_ADD_RES>,   cudaFuncAttributeMaxDynamicSharedMemorySize, SMEM_BYTES);

    dim3 redGrid(B_IMG, NBLK_RED);
    dim3 g256 (NPIX / BM, C_CH  / BN);   // (392, 2)
    dim3 g1024(NPIX / BM, HID_CH / BN);  // (392, 8)
    const int TP_BLKS = (B_IMG * C_CH * HW / 4 + 255) / 256;

    // launches #1-#3, then #4 = c1 GEMM (ncu profiles the 4th launch)
    wsplit_all_k<<<dim3(NWB / 256, 6), 256>>>(c1_w, c21_w, c22_w, c3_w, fc1_w, fc2_w, wh, wl);
    reduce_part_k<<<redGrid, 256>>>(x, part);
    finalize_k<<<1, 32>>>(part, st0);
    mma_gemm_k<IN_GN, OUT_RAW><<<g256, 256, SMEM_BYTES>>>(
        wh + O_C1, wl + O_C1, x, c1_b, st0, n1_w, n1_b, nullptr, bufA, C_CH, C_CH);

    reduce_part_k<<<redGrid, 256>>>(bufA, part);
    finalize_k<<<1, 32>>>(part, st1);
    tpass_k<<<TP_BLKS, 256>>>(bufA, st1, asn1_w, asn1_b, tpack);
    mma_gemm_k<IN_PSHIFT_W, OUT_GELU><<<g256, 256, SMEM_BYTES>>>(
        wh + O_C21, wl + O_C21, tpack, c21_b, nullptr, nullptr, nullptr, nullptr, bufS, C_CH, C_CH);
    mma_gemm_k<IN_PSHIFT_H, OUT_GELU_ACC><<<g256, 256, SMEM_BYTES>>>(
        wh + O_C22, wl + O_C22, tpack, c22_b, nullptr, nullptr, nullptr, nullptr, bufS, C_CH, C_CH);

    reduce_part_k<<<redGrid, 256>>>(bufS, part);
    finalize_k<<<1, 32>>>(part, st2);
    mma_gemm_k<IN_GN, OUT_ADD_RES><<<g256, 256, SMEM_BYTES>>>(
        wh + O_C3, wl + O_C3, bufS, c3_b, st2, asn2_w, asn2_b, x, bufX1, C_CH, C_CH);

    reduce_part_k<<<redGrid, 256>>>(bufX1, part);
    finalize_k<<<1, 32>>>(part, st3);
    mma_gemm_k<IN_GN, OUT_GELU_PACK><<<g1024, 256, SMEM_BYTES>>>(
        wh + O_FC1, wl + O_FC1, bufX1, fc1_b, st3, n2_w, n2_b, nullptr, bufHID, HID_CH, C_CH);
    mma_gemm_k<IN_PACKED, OUT_ADD_RES><<<g256, 256, SMEM_BYTES>>>(
        wh + O_FC2, wl + O_FC2, bufHID, fc2_b, nullptr, nullptr, nullptr, bufX1, out, C_CH, HID_CH);
}

// round 7
// speedup vs baseline: 1.2392x; 1.2392x over previous
#include <cuda_runtime.h>
#include <cuda_fp16.h>
#include <math.h>
#include <stdint.h>

// ---------------- problem constants ----------------
#define B_IMG   16
#define C_CH    256
#define HID_CH  1024
#define HW      3136
#define W_DIM   56
#define PER_B   (C_CH * HW)
#define NPIX    (B_IMG * HW)          // 50176
#define NBLK_RED 128
#define SEG_RED (PER_B / NBLK_RED)    // 6272

// GEMM tile config (R5-proven skeleton: 2-stage, 80B stride)
#define BM 128
#define BN 128
#define BK 32
#define ASTRIDE 80
#define TBUF_B (BM * ASTRIDE)          // 10240
#define STAGE_B (3 * TBUF_B)           // A_hi | A_lo | B  = 30720
#define OFF_A_HI(s) ((s) * STAGE_B)
#define OFF_A_LO(s) ((s) * STAGE_B + TBUF_B)
#define OFF_B(s)    ((s) * STAGE_B + 2 * TBUF_B)
#define EP_STRIDE 132
#define SMEM_BYTES 69632               // max(2*STAGE_B=61440, ep=128*132*4=67584) padded

// ---------------- scratch ----------------
__device__ float g_bufA[B_IMG * C_CH * HW];
__device__ float g_bufS[B_IMG * C_CH * HW];
__device__ float g_bufX1[B_IMG * C_CH * HW];
__device__ unsigned g_bufHID[B_IMG * HID_CH * HW];   // packed fp16 hi|lo<<16
__device__ unsigned g_tpack[B_IMG * C_CH * HW];      // packed fp16 t = gelu(GN(bufA))
__device__ float2 g_part[B_IMG * NBLK_RED];
__device__ float2 g_stats[4 * B_IMG];
#define WTOT (4*C_CH*C_CH + 2*HID_CH*C_CH)
__device__ __half g_wh[WTOT];                        // weights single fp16

__device__ __forceinline__ float gelu_f(float v) {
    return 0.5f * v * (1.0f + erff(v * 0.7071067811865476f));
}
// fp16 hi/lo packed split: hi in low 16 bits, lo in high 16 bits
__device__ __forceinline__ unsigned pack_split(float v) {
    __half h = __float2half_rn(v);
    __half l = __float2half_rn(v - __half2float(h));
    return (unsigned)__half_as_ushort(h) | ((unsigned)__half_as_ushort(l) << 16);
}
__device__ __forceinline__ unsigned smem_u32(const void* p) {
    unsigned a;
    asm("{ .reg .u64 t; cvta.to.shared.u64 t, %1; cvt.u32.u64 %0, t; }" : "=r"(a) : "l"(p));
    return a;
}
#define LDSM_X4(r, addr) \
    asm volatile("ldmatrix.sync.aligned.m8n8.x4.shared.b16 {%0,%1,%2,%3}, [%4];" \
                 : "=r"((r)[0]), "=r"((r)[1]), "=r"((r)[2]), "=r"((r)[3]) : "r"(addr))
#define MMA_F16(d, a, b0, b1) \
    asm volatile("mma.sync.aligned.m16n8k16.row.col.f32.f16.f16.f32 " \
                 "{%0,%1,%2,%3}, {%4,%5,%6,%7}, {%8,%9}, {%0,%1,%2,%3};" \
                 : "+f"((d)[0]), "+f"((d)[1]), "+f"((d)[2]), "+f"((d)[3]) \
                 : "r"((a)[0]), "r"((a)[1]), "r"((a)[2]), "r"((a)[3]), "r"(b0), "r"(b1))
#define CP_ASYNC16(saddr, gptr) \
    asm volatile("cp.async.cg.shared.global [%0], [%1], 16;" :: "r"(saddr), "l"(gptr) : "memory")
#define CP_COMMIT() asm volatile("cp.async.commit_group;" ::: "memory")
#define CP_WAIT0()  asm volatile("cp.async.wait_group 0;" ::: "memory")

// ---------------- GN reductions ----------------
__global__ void reduce_part_k(const float* __restrict__ src, float2* __restrict__ part) {
    int b = blockIdx.x, blk = blockIdx.y;
    const float4* p = (const float4*)(src + (size_t)b * PER_B + blk * SEG_RED);
    float s = 0.f, ss = 0.f;
    for (int i = threadIdx.x; i < SEG_RED / 4; i += 256) {
        float4 v = p[i];
        s  += v.x + v.y + v.z + v.w;
        ss += v.x*v.x + v.y*v.y + v.z*v.z + v.w*v.w;
    }
    __shared__ float sh1[256], sh2[256];
    int t = threadIdx.x;
    sh1[t] = s; sh2[t] = ss;
    __syncthreads();
    for (int st = 128; st > 0; st >>= 1) {
        if (t < st) { sh1[t] += sh1[t+st]; sh2[t] += sh2[t+st]; }
        __syncthreads();
    }
    if (t == 0) part[b * NBLK_RED + blk] = make_float2(sh1[0], sh2[0]);
}

__global__ void finalize_k(const float2* __restrict__ part, float2* __restrict__ stats) {
    int b = threadIdx.x;
    if (b >= B_IMG) return;
    float s = 0.f, ss = 0.f;
    for (int i = 0; i < NBLK_RED; i++) {
        float2 p = part[b * NBLK_RED + i];
        s += p.x; ss += p.y;
    }
    const float n = (float)PER_B;
    float mean = s / n;
    float var  = ss / n - mean * mean;
    stats[b] = make_float2(mean, rsqrtf(var + 1e-5f));
}

// ---------------- all 6 weight converts in ONE launch (fp16 single) ------
__global__ void wsplit_all_k(const float* s0, const float* s1, const float* s2,
                             const float* s3, const float* s4, const float* s5,
                             __half* __restrict__ wh) {
    const int NWS = C_CH * C_CH, NWB = HID_CH * C_CH;
    const float* srcs[6] = { s0, s1, s2, s3, s4, s5 };
    const int offs[6] = { 0, NWS, 2*NWS, 3*NWS, 4*NWS, 4*NWS + NWB };
    const int ns[6]   = { NWS, NWS, NWS, NWS, NWB, NWB };
    int g = blockIdx.y;
    int i = blockIdx.x * 256 + threadIdx.x;
    if (i < ns[g]) wh[offs[g] + i] = __float2half_rn(srcs[g][i]);
}

// ---------------- tpass: t = gelu(GN(bufA)) -> packed fp16 u32 ----------
__global__ void tpass_k(const float* __restrict__ src, const float2* __restrict__ stats,
                        const float* __restrict__ gamma, const float* __restrict__ beta,
                        unsigned* __restrict__ dst) {
    int i4 = blockIdx.x * 256 + threadIdx.x;
    const int total4 = B_IMG * C_CH * HW / 4;
    if (i4 >= total4) return;
    int i = i4 * 4;
    int b = i / PER_B;
    int r = i - b * PER_B;
    int c = r / HW;
    float2 st = stats[b];
    float g = gamma[c], be = beta[c];
    float4 v = ((const float4*)src)[i4];
    uint4 o;
    o.x = pack_split(gelu_f((v.x - st.x) * st.y * g + be));
    o.y = pack_split(gelu_f((v.y - st.x) * st.y * g + be));
    o.z = pack_split(gelu_f((v.z - st.x) * st.y * g + be));
    o.w = pack_split(gelu_f((v.w - st.x) * st.y * g + be));
    ((uint4*)dst)[i4] = o;
}

// ---------------- fused HMMA GEMM ----------------
#define IN_GN        0
#define IN_PACKED    1
#define IN_PSHIFT_W  2
#define IN_PSHIFT_H  3
#define OUT_RAW       0
#define OUT_GELU      1
#define OUT_GELU_ACC  2
#define OUT_ADD_RES   3
#define OUT_GELU_PACK 4

template<int IM>
__device__ __forceinline__ unsigned load_u(const void* __restrict__ Bsrc, int K, int b_img,
                                           int hw, int hh, int ww, float mean, float rstd,
                                           const float* __restrict__ gamma,
                                           const float* __restrict__ beta, int c, int group) {
    if (IM == IN_GN) {
        float v = ((const float*)Bsrc)[((size_t)b_img * K + c) * HW + hw];
        return __float_as_uint((v - mean) * rstd * gamma[c] + beta[c]);
    } else if (IM == IN_PACKED) {
        return ((const unsigned*)Bsrc)[((size_t)b_img * K + c) * HW + hw];
    } else if (IM == IN_PSHIFT_W) {
        int s = 3 - c / group;
        int w2 = ww + s;
        if (w2 < 0 || w2 >= W_DIM) return 0u;
        return ((const unsigned*)Bsrc)[((size_t)b_img * K + c) * HW + hh * W_DIM + w2];
    } else {
        int s = 3 - c / group;
        int h2 = hh + s;
        if (h2 < 0 || h2 >= W_DIM) return 0u;
        return ((const unsigned*)Bsrc)[((size_t)b_img * K + c) * HW + h2 * W_DIM + ww];
    }
}

template<int IM>
__device__ __forceinline__ void sts_pair(unsigned ah, unsigned al, unsigned off,
                                         unsigned a0, unsigned a1) {
    unsigned hp, lp;
    if (IM == IN_GN) {
        float v0 = __uint_as_float(a0), v1 = __uint_as_float(a1);
        __half h0 = __float2half_rn(v0);
        __half h1 = __float2half_rn(v1);
        __half l0 = __float2half_rn(v0 - __half2float(h0));
        __half l1 = __float2half_rn(v1 - __half2float(h1));
        hp = (unsigned)__half_as_ushort(h0) | ((unsigned)__half_as_ushort(h1) << 16);
        lp = (unsigned)__half_as_ushort(l0) | ((unsigned)__half_as_ushort(l1) << 16);
    } else {
        hp = __byte_perm(a0, a1, 0x5410);
        lp = __byte_perm(a0, a1, 0x7632);
    }
    asm volatile("st.shared.b32 [%0], %1;" :: "r"(ah + off), "r"(hp) : "memory");
    asm volatile("st.shared.b32 [%0], %1;" :: "r"(al + off), "r"(lp) : "memory");
}

template<int IM, int OM>
__global__ void __launch_bounds__(256, 2) mma_gemm_k(
    const __half* __restrict__ Wh,
    const void* __restrict__ Bsrc, const float* __restrict__ bias,
    const float2* __restrict__ stats, const float* __restrict__ gamma,
    const float* __restrict__ beta, const float* __restrict__ res,
    void* __restrict__ out, int Mout, int K)
{
    extern __shared__ char smem[];
    const unsigned sbase = smem_u32(smem);

    const int tid  = threadIdx.x;
    const int wid  = tid >> 5;
    const int lane = tid & 31;
    const int warp_m = wid & 3;
    const int warp_n = wid >> 2;

    const int px   = tid & 127;
    const int hseg = tid >> 7;
    const int gpix = blockIdx.x * BM + px;
    const int b_img = gpix / HW;
    const int hw    = gpix - b_img * HW;
    const int hh    = hw / W_DIM;
    const int ww    = hw - hh * W_DIM;
    float mean = 0.f, rstd = 0.f;
    if (IM == IN_GN) { float2 st = stats[b_img]; mean = st.x; rstd = st.y; }
    const int group = (K + 6) / 7;
    const int n0 = blockIdx.y * BN;
    const int nch = K / BK;

    // B loader: 2 x 16B per thread (single fp16 weight buffer)
    const int brow0 = tid >> 2;
    const int bq0   = tid & 3;
    const int brow1 = (tid + 256) >> 2;
    const int bq1   = (tid + 256) & 3;

    float acc[2][8][4];
    #pragma unroll
    for (int i = 0; i < 2; i++)
        #pragma unroll
        for (int j = 0; j < 8; j++)
            #pragma unroll
            for (int q = 0; q < 4; q++) acc[i][j][q] = 0.f;

    unsigned areg[16];

    // ---- prologue: chunk 0 ----
    {
        unsigned bb = sbase + OFF_B(0);
        CP_ASYNC16(bb + brow0 * ASTRIDE + bq0 * 16, Wh + (size_t)(n0 + brow0) * K + bq0 * 8);
        CP_ASYNC16(bb + brow1 * ASTRIDE + bq1 * 16, Wh + (size_t)(n0 + brow1) * K + bq1 * 8);
        CP_COMMIT();
        #pragma unroll
        for (int j = 0; j < 16; j++)
            areg[j] = load_u<IM>(Bsrc, K, b_img, hw, hh, ww, mean, rstd, gamma, beta,
                                 hseg * 16 + j, group);
        unsigned ah = sbase + OFF_A_HI(0), al = sbase + OFF_A_LO(0);
        #pragma unroll
        for (int j = 0; j < 16; j += 2)
            sts_pair<IM>(ah, al, px * ASTRIDE + (hseg * 16 + j) * 2, areg[j], areg[j+1]);
        CP_WAIT0();
        __syncthreads();
    }

    const unsigned a_lrow = warp_m * 32 + (lane & 15);
    const unsigned a_lcol = (lane >> 4) * 16;
    const unsigned b_lrow = warp_n * 64 + ((lane & 16) >> 1) + (lane & 7);
    const unsigned b_lcol = ((lane >> 3) & 1) * 16;

    for (int i = 0; i < nch; ++i) {
        const int cur = i & 1, nxt = cur ^ 1;
        const bool more = (i + 1 < nch);
        if (more) {
            const int k1 = (i + 1) * BK;
            unsigned bb = sbase + OFF_B(nxt);
            CP_ASYNC16(bb + brow0 * ASTRIDE + bq0 * 16, Wh + (size_t)(n0 + brow0) * K + k1 + bq0 * 8);
            CP_ASYNC16(bb + brow1 * ASTRIDE + bq1 * 16, Wh + (size_t)(n0 + brow1) * K + k1 + bq1 * 8);
            CP_COMMIT();
            #pragma unroll
            for (int j = 0; j < 16; j++)
                areg[j] = load_u<IM>(Bsrc, K, b_img, hw, hh, ww, mean, rstd, gamma, beta,
                                     k1 + hseg * 16 + j, group);
        }

        // ---- compute chunk i: D += Ah*B + Al*B ----
        const unsigned Ah = sbase + OFF_A_HI(cur), Al = sbase + OFF_A_LO(cur);
        const unsigned Bb = sbase + OFF_B(cur);
        #pragma unroll
        for (int ks = 0; ks < 2; ++ks) {
            unsigned ahf[2][4], alf[2][4];
            #pragma unroll
            for (int mi = 0; mi < 2; ++mi) {
                unsigned off = (a_lrow + mi * 16) * ASTRIDE + ks * 32 + a_lcol;
                LDSM_X4(ahf[mi], Ah + off);
                LDSM_X4(alf[mi], Al + off);
            }
            #pragma unroll
            for (int nip = 0; nip < 4; ++nip) {
                unsigned bf[4];
                unsigned off = (b_lrow + nip * 16) * ASTRIDE + ks * 32 + b_lcol;
                LDSM_X4(bf, Bb + off);
                #pragma unroll
                for (int mi = 0; mi < 2; ++mi) {
                    #pragma unroll
                    for (int h = 0; h < 2; ++h) {
                        float* d = acc[mi][nip * 2 + h];
                        MMA_F16(d, ahf[mi], bf[2*h], bf[2*h+1]);
                        MMA_F16(d, alf[mi], bf[2*h], bf[2*h+1]);
                    }
                }
            }
        }

        if (more) {
            unsigned ah = sbase + OFF_A_HI(nxt), al = sbase + OFF_A_LO(nxt);
            #pragma unroll
            for (int j = 0; j < 16; j += 2)
                sts_pair<IM>(ah, al, px * ASTRIDE + (hseg * 16 + j) * 2, areg[j], areg[j+1]);
            CP_WAIT0();
            __syncthreads();
        }
    }

    // ---- epilogue via smem transpose ----
    __syncthreads();
    float* ep = (float*)smem;
    const int r4 = lane >> 2;
    const int c2 = (lane & 3) * 2;
    #pragma unroll
    for (int mi = 0; mi < 2; ++mi) {
        #pragma unroll
        for (int ni = 0; ni < 8; ++ni) {
            int m = warp_m * 32 + mi * 16 + r4;
            int n = warp_n * 64 + ni * 8 + c2;
            ep[n * EP_STRIDE + m]           = acc[mi][ni][0];
            ep[(n + 1) * EP_STRIDE + m]     = acc[mi][ni][1];
            ep[n * EP_STRIDE + m + 8]       = acc[mi][ni][2];
            ep[(n + 1) * EP_STRIDE + m + 8] = acc[mi][ni][3];
        }
    }
    __syncthreads();

    #pragma unroll 4
    for (int it = 0; it < 64; ++it) {
        int flat = it * 256 + tid;
        int nl = flat >> 7;
        int m  = flat & 127;
        int g  = blockIdx.x * BM + m;
        int be = g / HW;
        int hwe = g - be * HW;
        int n  = n0 + nl;
        float v = ep[nl * EP_STRIDE + m] + bias[n];
        size_t idx = ((size_t)be * Mout + n) * HW + hwe;
        if (OM == OUT_RAW)            ((float*)out)[idx] = v;
        else if (OM == OUT_GELU)      ((float*)out)[idx] = gelu_f(v);
        else if (OM == OUT_GELU_ACC)  ((float*)out)[idx] += gelu_f(v);
        else if (OM == OUT_ADD_RES)   ((float*)out)[idx] = v + res[idx];
        else                          ((unsigned*)out)[idx] = pack_split(gelu_f(v));
    }
}

// ---------------- launch ----------------
extern "C" void kernel_launch(void* const* d_in, const int* in_sizes, int n_in,
                              void* d_out, int out_size)
{
    const float* x      = (const float*)d_in[0];
    const float* n1_w   = (const float*)d_in[1];
    const float* n1_b   = (const float*)d_in[2];
    const float* c1_w   = (const float*)d_in[3];
    const float* c1_b   = (const float*)d_in[4];
    const float* asn1_w = (const float*)d_in[5];
    const float* asn1_b = (const float*)d_in[6];
    const float* c21_w  = (const float*)d_in[7];
    const float* c21_b  = (const float*)d_in[8];
    const float* c22_w  = (const float*)d_in[9];
    const float* c22_b  = (const float*)d_in[10];
    const float* asn2_w = (const float*)d_in[11];
    const float* asn2_b = (const float*)d_in[12];
    const float* c3_w   = (const float*)d_in[13];
    const float* c3_b   = (const float*)d_in[14];
    const float* n2_w   = (const float*)d_in[15];
    const float* n2_b   = (const float*)d_in[16];
    const float* fc1_w  = (const float*)d_in[17];
    const float* fc1_b  = (const float*)d_in[18];
    const float* fc2_w  = (const float*)d_in[19];
    const float* fc2_b  = (const float*)d_in[20];
    float* out = (float*)d_out;

    float *bufA, *bufS, *bufX1;
    unsigned *bufHID, *tpack;
    float2 *part, *stats;
    __half *wh;
    cudaGetSymbolAddress((void**)&bufA,   g_bufA);
    cudaGetSymbolAddress((void**)&bufS,   g_bufS);
    cudaGetSymbolAddress((void**)&bufX1,  g_bufX1);
    cudaGetSymbolAddress((void**)&bufHID, g_bufHID);
    cudaGetSymbolAddress((void**)&tpack,  g_tpack);
    cudaGetSymbolAddress((void**)&part,   g_part);
    cudaGetSymbolAddress((void**)&stats,  g_stats);
    cudaGetSymbolAddress((void**)&wh,     g_wh);

    float2* st0 = stats + 0 * B_IMG;
    float2* st1 = stats + 1 * B_IMG;
    float2* st2 = stats + 2 * B_IMG;
    float2* st3 = stats + 3 * B_IMG;

    const int NWS = C_CH * C_CH, NWB = HID_CH * C_CH;
    const int O_C1 = 0, O_C21 = NWS, O_C22 = 2*NWS, O_C3 = 3*NWS,
              O_FC1 = 4*NWS, O_FC2 = 4*NWS + NWB;

    cudaFuncSetAttribute(mma_gemm_k<IN_GN,       OUT_RAW>,       cudaFuncAttributeMaxDynamicSharedMemorySize, SMEM_BYTES);
    cudaFuncSetAttribute(mma_gemm_k<IN_PSHIFT_W, OUT_GELU>,      cudaFuncAttributeMaxDynamicSharedMemorySize, SMEM_BYTES);
    cudaFuncSetAttribute(mma_gemm_k<IN_PSHIFT_H, OUT_GELU_ACC>,  cudaFuncAttributeMaxDynamicSharedMemorySize, SMEM_BYTES);
    cudaFuncSetAttribute(mma_gemm_k<IN_GN,       OUT_ADD_RES>,   cudaFuncAttributeMaxDynamicSharedMemorySize, SMEM_BYTES);
    cudaFuncSetAttribute(mma_gemm_k<IN_GN,       OUT_GELU_PACK>, cudaFuncAttributeMaxDynamicSharedMemorySize, SMEM_BYTES);
    cudaFuncSetAttribute(mma_gemm_k<IN_PACKED,   OUT_ADD_RES>,   cudaFuncAttributeMaxDynamicSharedMemorySize, SMEM_BYTES);

    dim3 redGrid(B_IMG, NBLK_RED);
    dim3 g256 (NPIX / BM, C_CH  / BN);   // (392, 2)
    dim3 g1024(NPIX / BM, HID_CH / BN);  // (392, 8)
    const int TP_BLKS = (B_IMG * C_CH * HW / 4 + 255) / 256;

    // launches #1-#3, then #4 = c1 GEMM (ncu profiles the 4th launch)
    wsplit_all_k<<<dim3(NWB / 256, 6), 256>>>(c1_w, c21_w, c22_w, c3_w, fc1_w, fc2_w, wh);
    reduce_part_k<<<redGrid, 256>>>(x, part);
    finalize_k<<<1, 32>>>(part, st0);
    mma_gemm_k<IN_GN, OUT_RAW><<<g256, 256, SMEM_BYTES>>>(
        wh + O_C1, x, c1_b, st0, n1_w, n1_b, nullptr, bufA, C_CH, C_CH);

    reduce_part_k<<<redGrid, 256>>>(bufA, part);
    finalize_k<<<1, 32>>>(part, st1);
    tpass_k<<<TP_BLKS, 256>>>(bufA, st1, asn1_w, asn1_b, tpack);
    mma_gemm_k<IN_PSHIFT_W, OUT_GELU><<<g256, 256, SMEM_BYTES>>>(
        wh + O_C21, tpack, c21_b, nullptr, nullptr, nullptr, nullptr, bufS, C_CH, C_CH);
    mma_gemm_k<IN_PSHIFT_H, OUT_GELU_ACC><<<g256, 256, SMEM_BYTES>>>(
        wh + O_C22, tpack, c22_b, nullptr, nullptr, nullptr, nullptr, bufS, C_CH, C_CH);

    reduce_part_k<<<redGrid, 256>>>(bufS, part);
    finalize_k<<<1, 32>>>(part, st2);
    mma_gemm_k<IN_GN, OUT_ADD_RES><<<g256, 256, SMEM_BYTES>>>(
        wh + O_C3, bufS, c3_b, st2, asn2_w, asn2_b, x, bufX1, C_CH, C_CH);

    reduce_part_k<<<redGrid, 256>>>(bufX1, part);
    finalize_k<<<1, 32>>>(part, st3);
    mma_gemm_k<IN_GN, OUT_GELU_PACK><<<g1024, 256, SMEM_BYTES>>>(
        wh + O_FC1, bufX1, fc1_b, st3, n2_w, n2_b, nullptr, bufHID, HID_CH, C_CH);
    mma_gemm_k<IN_PACKED, OUT_ADD_RES><<<g256, 256, SMEM_BYTES>>>(
        wh + O_FC2, bufHID, fc2_b, nullptr, nullptr, nullptr, bufX1, out, C_CH, HID_CH);
}

// round 8
// speedup vs baseline: 1.4423x; 1.1639x over previous
#include <cuda_runtime.h>
#include <cuda_fp16.h>
#include <math.h>
#include <stdint.h>

// ---------------- problem constants ----------------
#define B_IMG   16
#define C_CH    256
#define HID_CH  1024
#define HW      3136
#define W_DIM   56
#define PER_B   (C_CH * HW)
#define NPIX    (B_IMG * HW)          // 50176
#define NBLK_RED 128
#define SEG_RED (PER_B / NBLK_RED)    // 6272
#define NELEM   (B_IMG * C_CH * HW)   // 12845056

// GEMM tile config
#define BM 128
#define BN 128
#define BK 32
#define AROW_B  272                    // 128 px * 2B + 16 pad  (k-major A rows)
#define ABUF_B  (BK * AROW_B)          // 8704
#define BROW_B  80                     // 32 k * 2B + 16 pad
#define BBUF_B  (BN * BROW_B)          // 10240
#define STAGE_B (2 * ABUF_B + BBUF_B)  // 27648
#define OFF_AHI(s) ((s) * STAGE_B)
#define OFF_ALO(s) ((s) * STAGE_B + ABUF_B)
#define OFF_BW(s)  ((s) * STAGE_B + 2 * ABUF_B)
#define EP_STRIDE 132
#define SMEM_BYTES 69632               // >= max(2*STAGE_B=55296, ep 67584)

// ---------------- scratch ----------------
__device__ float g_bufA[NELEM];
__device__ float g_bufS[NELEM];
__device__ float g_bufX1[NELEM];
__device__ __half g_pAh[NELEM];         // generic GN-packed A planes (hi/lo)
__device__ __half g_pAl[NELEM];
__device__ __half g_lrh[NELEM];         // pre-shifted gelu(GN(bufA)) planes
__device__ __half g_lrl[NELEM];
__device__ __half g_tdh[NELEM];
__device__ __half g_tdl[NELEM];
__device__ __half g_hidh[B_IMG * HID_CH * HW];
__device__ __half g_hidl[B_IMG * HID_CH * HW];
__device__ float2 g_part[B_IMG * NBLK_RED];
__device__ float2 g_stats[4 * B_IMG];
#define WTOT (4*C_CH*C_CH + 2*HID_CH*C_CH)   // 786432
__device__ __half g_wh[WTOT];

__device__ __forceinline__ float gelu_f(float v) {
    return 0.5f * v * (1.0f + erff(v * 0.7071067811865476f));
}
__device__ __forceinline__ unsigned smem_u32(const void* p) {
    unsigned a;
    asm("{ .reg .u64 t; cvta.to.shared.u64 t, %1; cvt.u32.u64 %0, t; }" : "=r"(a) : "l"(p));
    return a;
}
#define LDSM_X4(r, addr) \
    asm volatile("ldmatrix.sync.aligned.m8n8.x4.shared.b16 {%0,%1,%2,%3}, [%4];" \
                 : "=r"((r)[0]), "=r"((r)[1]), "=r"((r)[2]), "=r"((r)[3]) : "r"(addr))
#define LDSM_X4_T(r, addr) \
    asm volatile("ldmatrix.sync.aligned.m8n8.x4.trans.shared.b16 {%0,%1,%2,%3}, [%4];" \
                 : "=r"((r)[0]), "=r"((r)[1]), "=r"((r)[2]), "=r"((r)[3]) : "r"(addr))
#define MMA_F16(d, a, b0, b1) \
    asm volatile("mma.sync.aligned.m16n8k16.row.col.f32.f16.f16.f32 " \
                 "{%0,%1,%2,%3}, {%4,%5,%6,%7}, {%8,%9}, {%0,%1,%2,%3};" \
                 : "+f"((d)[0]), "+f"((d)[1]), "+f"((d)[2]), "+f"((d)[3]) \
                 : "r"((a)[0]), "r"((a)[1]), "r"((a)[2]), "r"((a)[3]), "r"(b0), "r"(b1))
#define CP_ASYNC16(saddr, gptr) \
    asm volatile("cp.async.cg.shared.global [%0], [%1], 16;" :: "r"(saddr), "l"(gptr) : "memory")
#define CP_COMMIT() asm volatile("cp.async.commit_group;" ::: "memory")
#define CP_WAIT0()  asm volatile("cp.async.wait_group 0;" ::: "memory")

// ---------------- GN reductions ----------------
__global__ void reduce_part_k(const float* __restrict__ src, float2* __restrict__ part) {
    int b = blockIdx.x, blk = blockIdx.y;
    const float4* p = (const float4*)(src + (size_t)b * PER_B + blk * SEG_RED);
    float s = 0.f, ss = 0.f;
    for (int i = threadIdx.x; i < SEG_RED / 4; i += 256) {
        float4 v = p[i];
        s  += v.x + v.y + v.z + v.w;
        ss += v.x*v.x + v.y*v.y + v.z*v.z + v.w*v.w;
    }
    __shared__ float sh1[256], sh2[256];
    int t = threadIdx.x;
    sh1[t] = s; sh2[t] = ss;
    __syncthreads();
    for (int st = 128; st > 0; st >>= 1) {
        if (t < st) { sh1[t] += sh1[t+st]; sh2[t] += sh2[t+st]; }
        __syncthreads();
    }
    if (t == 0) part[b * NBLK_RED + blk] = make_float2(sh1[0], sh2[0]);
}

__global__ void finalize_k(const float2* __restrict__ part, float2* __restrict__ stats) {
    int b = threadIdx.x;
    if (b >= B_IMG) return;
    float s = 0.f, ss = 0.f;
    for (int i = 0; i < NBLK_RED; i++) {
        float2 p = part[b * NBLK_RED + i];
        s += p.x; ss += p.y;
    }
    const float n = (float)PER_B;
    float mean = s / n;
    float var  = ss / n - mean * mean;
    stats[b] = make_float2(mean, rsqrtf(var + 1e-5f));
}

// ---------------- pack bodies ----------------
__device__ __forceinline__ void pack_gn_body(const float* __restrict__ src,
                                             const float2* __restrict__ stats,
                                             const float* __restrict__ gamma,
                                             const float* __restrict__ beta,
                                             __half* __restrict__ dhi, __half* __restrict__ dlo,
                                             int i4) {
    int i = i4 * 4;
    int b = i / PER_B;
    int r = i - b * PER_B;
    int c = r / HW;
    float2 st = stats[b];
    float g = gamma[c], be = beta[c];
    float4 v = ((const float4*)src)[i4];
    float f0 = (v.x - st.x) * st.y * g + be;
    float f1 = (v.y - st.x) * st.y * g + be;
    float f2 = (v.z - st.x) * st.y * g + be;
    float f3 = (v.w - st.x) * st.y * g + be;
    __half h0 = __float2half_rn(f0), h1 = __float2half_rn(f1);
    __half h2 = __float2half_rn(f2), h3 = __float2half_rn(f3);
    ((ushort4*)dhi)[i4] = make_ushort4(__half_as_ushort(h0), __half_as_ushort(h1),
                                       __half_as_ushort(h2), __half_as_ushort(h3));
    __half l0 = __float2half_rn(f0 - __half2float(h0));
    __half l1 = __float2half_rn(f1 - __half2float(h1));
    __half l2 = __float2half_rn(f2 - __half2float(h2));
    __half l3 = __float2half_rn(f3 - __half2float(h3));
    ((ushort4*)dlo)[i4] = make_ushort4(__half_as_ushort(l0), __half_as_ushort(l1),
                                       __half_as_ushort(l2), __half_as_ushort(l3));
}

__global__ void pack_gn_k(const float* __restrict__ src, const float2* __restrict__ stats,
                          const float* __restrict__ gamma, const float* __restrict__ beta,
                          __half* __restrict__ dhi, __half* __restrict__ dlo) {
    int i4 = blockIdx.x * 256 + threadIdx.x;
    if (i4 < NELEM / 4) pack_gn_body(src, stats, gamma, beta, dhi, dlo, i4);
}

// combo: y=0 -> pack_gn(x); y=1 -> weight fp16 conversion
__global__ void combo_pack_wconv_k(const float* __restrict__ x, const float2* __restrict__ stats,
                                   const float* __restrict__ gamma, const float* __restrict__ beta,
                                   __half* __restrict__ dhi, __half* __restrict__ dlo,
                                   const float* w0, const float* w1, const float* w2,
                                   const float* w3, const float* w4, const float* w5,
                                   __half* __restrict__ wdst) {
    if (blockIdx.y == 0) {
        int i4 = blockIdx.x * 256 + threadIdx.x;
        if (i4 < NELEM / 4) pack_gn_body(x, stats, gamma, beta, dhi, dlo, i4);
    } else {
        int i = blockIdx.x * 256 + threadIdx.x;
        if (i < 262144) {
            const float* srcs[4] = { w0, w1, w2, w3 };
            wdst[i] = __float2half_rn(srcs[i >> 16][i & 65535]);
        } else if (i < 524288) {
            wdst[i] = __float2half_rn(w4[i - 262144]);
        } else if (i < 786432) {
            wdst[i] = __float2half_rn(w5[i - 524288]);
        }
    }
}

// shift pre-pass: lr/td planes = gelu(GN(bufA)) shifted, zero-filled
__global__ void pack_shift_k(const float* __restrict__ src, const float2* __restrict__ stats,
                             const float* __restrict__ gamma, const float* __restrict__ beta,
                             __half* __restrict__ lrh, __half* __restrict__ lrl,
                             __half* __restrict__ tdh, __half* __restrict__ tdl) {
    int idx = blockIdx.x * 256 + threadIdx.x;
    if (idx >= NELEM) return;
    int b = idx / PER_B;
    int r = idx - b * PER_B;
    int c = r / HW;
    int hw = r - c * HW;
    int h = hw / W_DIM, w = hw - h * W_DIM;
    float2 st = stats[b];
    float g = gamma[c], be = beta[c];
    int s = 3 - c / 37;                 // group = ceil(256/7) = 37
    const float* base = src + (size_t)(b * C_CH + c) * HW;
    float vlr = 0.f, vtd = 0.f;
    int w2 = w + s;
    if (w2 >= 0 && w2 < W_DIM)
        vlr = gelu_f((base[h * W_DIM + w2] - st.x) * st.y * g + be);
    int h2 = h + s;
    if (h2 >= 0 && h2 < W_DIM)
        vtd = gelu_f((base[h2 * W_DIM + w] - st.x) * st.y * g + be);
    __half a = __float2half_rn(vlr);
    lrh[idx] = a;
    lrl[idx] = __float2half_rn(vlr - __half2float(a));
    __half d = __float2half_rn(vtd);
    tdh[idx] = d;
    tdl[idx] = __float2half_rn(vtd - __half2float(d));
}

// ---------------- pure cp.async HMMA GEMM ----------------
#define OUT_RAW        0
#define OUT_GELU       1
#define OUT_GELU_ACC   2
#define OUT_ADD_RES    3
#define OUT_GELU_PACK2 4

template<int OM>
__global__ void __launch_bounds__(256, 2) gemm_k(
    const __half* __restrict__ Ahi, const __half* __restrict__ Alo,   // planes [b*K+c][hw]
    const __half* __restrict__ W,                                      // [Mout][K]
    const float* __restrict__ bias, const float* __restrict__ res,
    float* __restrict__ out, __half* __restrict__ o2h, __half* __restrict__ o2l,
    int Mout, int K)
{
    extern __shared__ char smem[];
    const unsigned sb = smem_u32(smem);

    const int tid  = threadIdx.x;
    const int wid  = tid >> 5;
    const int lane = tid & 31;
    const int warp_m = wid & 3;
    const int warp_n = wid >> 2;
    const int n0 = blockIdx.y * BN;
    const int nch = K / BK;

    // A cp.async mapping: 2 slots/thread per plane; slot idx -> (k, 8px-block)
    const int ak0 = tid >> 4,        ab0 = tid & 15;
    const int ak1 = (tid + 256) >> 4, ab1 = (tid + 256) & 15;
    int gp0 = blockIdx.x * BM + ab0 * 8;
    int bb0 = gp0 / HW;
    size_t abase0 = (size_t)bb0 * K * HW + (gp0 - bb0 * HW);
    int gp1 = blockIdx.x * BM + ab1 * 8;
    int bb1 = gp1 / HW;
    size_t abase1 = (size_t)bb1 * K * HW + (gp1 - bb1 * HW);
    const unsigned as0 = ak0 * AROW_B + ab0 * 16;
    const unsigned as1 = ak1 * AROW_B + ab1 * 16;
    // B mapping
    const int brow0 = tid >> 2,        bq0 = tid & 3;
    const int brow1 = (tid + 256) >> 2, bq1 = (tid + 256) & 3;
    const unsigned bso0 = brow0 * BROW_B + bq0 * 16;
    const unsigned bso1 = brow1 * BROW_B + bq1 * 16;
    const size_t wrow0 = (size_t)(n0 + brow0) * K;
    const size_t wrow1 = (size_t)(n0 + brow1) * K;

    float acc[2][8][4];
    #pragma unroll
    for (int i = 0; i < 2; i++)
        #pragma unroll
        for (int j = 0; j < 8; j++)
            #pragma unroll
            for (int q = 0; q < 4; q++) acc[i][j][q] = 0.f;

    // frag address components
    const unsigned a_klane = ((lane >> 4) & 1) * 8 + (lane & 7);        // 0..15
    const unsigned a_mcolB = (warp_m * 32 + ((lane >> 3) & 1) * 8) * 2; // bytes
    const unsigned b_lrow  = warp_n * 64 + ((lane & 16) >> 1) + (lane & 7);
    const unsigned b_lcolB = ((lane >> 3) & 1) * 16;

    // prologue: chunk 0
    {
        CP_ASYNC16(sb + OFF_AHI(0) + as0, Ahi + abase0 + (size_t)ak0 * HW);
        CP_ASYNC16(sb + OFF_AHI(0) + as1, Ahi + abase1 + (size_t)ak1 * HW);
        CP_ASYNC16(sb + OFF_ALO(0) + as0, Alo + abase0 + (size_t)ak0 * HW);
        CP_ASYNC16(sb + OFF_ALO(0) + as1, Alo + abase1 + (size_t)ak1 * HW);
        CP_ASYNC16(sb + OFF_BW(0)  + bso0, W + wrow0 + bq0 * 8);
        CP_ASYNC16(sb + OFF_BW(0)  + bso1, W + wrow1 + bq1 * 8);
        CP_COMMIT();
        CP_WAIT0();
        __syncthreads();
    }

    for (int i = 0; i < nch; ++i) {
        const int cur = i & 1;
        if (i + 1 < nch) {
            const int nxt = cur ^ 1;
            const int kk = (i + 1) * BK;
            CP_ASYNC16(sb + OFF_AHI(nxt) + as0, Ahi + abase0 + (size_t)(kk + ak0) * HW);
            CP_ASYNC16(sb + OFF_AHI(nxt) + as1, Ahi + abase1 + (size_t)(kk + ak1) * HW);
            CP_ASYNC16(sb + OFF_ALO(nxt) + as0, Alo + abase0 + (size_t)(kk + ak0) * HW);
            CP_ASYNC16(sb + OFF_ALO(nxt) + as1, Alo + abase1 + (size_t)(kk + ak1) * HW);
            CP_ASYNC16(sb + OFF_BW(nxt)  + bso0, W + wrow0 + kk + bq0 * 8);
            CP_ASYNC16(sb + OFF_BW(nxt)  + bso1, W + wrow1 + kk + bq1 * 8);
            CP_COMMIT();
        }

        const unsigned Ah = sb + OFF_AHI(cur), Al = sb + OFF_ALO(cur), Bb = sb + OFF_BW(cur);
        #pragma unroll
        for (int ks = 0; ks < 2; ++ks) {
            unsigned ahf[2][4], alf[2][4];
            #pragma unroll
            for (int mi = 0; mi < 2; ++mi) {
                unsigned off = (ks * 16 + a_klane) * AROW_B + a_mcolB + mi * 32;
                LDSM_X4_T(ahf[mi], Ah + off);
                LDSM_X4_T(alf[mi], Al + off);
            }
            #pragma unroll
            for (int nip = 0; nip < 4; ++nip) {
                unsigned bf[4];
                unsigned off = (b_lrow + nip * 16) * BROW_B + ks * 32 + b_lcolB;
                LDSM_X4(bf, Bb + off);
                #pragma unroll
                for (int mi = 0; mi < 2; ++mi) {
                    #pragma unroll
                    for (int h = 0; h < 2; ++h) {
                        float* d = acc[mi][nip * 2 + h];
                        MMA_F16(d, ahf[mi], bf[2*h], bf[2*h+1]);
                        MMA_F16(d, alf[mi], bf[2*h], bf[2*h+1]);
                    }
                }
            }
        }

        CP_WAIT0();
        __syncthreads();
    }

    // epilogue via smem transpose
    float* ep = (float*)smem;
    const int r4 = lane >> 2;
    const int c2 = (lane & 3) * 2;
    #pragma unroll
    for (int mi = 0; mi < 2; ++mi) {
        #pragma unroll
        for (int ni = 0; ni < 8; ++ni) {
            int m = warp_m * 32 + mi * 16 + r4;
            int n = warp_n * 64 + ni * 8 + c2;
            ep[n * EP_STRIDE + m]           = acc[mi][ni][0];
            ep[(n + 1) * EP_STRIDE + m]     = acc[mi][ni][1];
            ep[n * EP_STRIDE + m + 8]       = acc[mi][ni][2];
            ep[(n + 1) * EP_STRIDE + m + 8] = acc[mi][ni][3];
        }
    }
    __syncthreads();

    #pragma unroll 4
    for (int it = 0; it < 64; ++it) {
        int flat = it * 256 + tid;
        int nl = flat >> 7;
        int m  = flat & 127;
        int g  = blockIdx.x * BM + m;
        int be = g / HW;
        int hwe = g - be * HW;
        int n  = n0 + nl;
        float v = ep[nl * EP_STRIDE + m] + bias[n];
        size_t idx = ((size_t)be * Mout + n) * HW + hwe;
        if (OM == OUT_RAW)            out[idx] = v;
        else if (OM == OUT_GELU)      out[idx] = gelu_f(v);
        else if (OM == OUT_GELU_ACC)  out[idx] += gelu_f(v);
        else if (OM == OUT_ADD_RES)   out[idx] = v + res[idx];
        else {
            float t = gelu_f(v);
            __half h = __float2half_rn(t);
            o2h[idx] = h;
            o2l[idx] = __float2half_rn(t - __half2float(h));
        }
    }
}

// ---------------- launch ----------------
extern "C" void kernel_launch(void* const* d_in, const int* in_sizes, int n_in,
                              void* d_out, int out_size)
{
    const float* x      = (const float*)d_in[0];
    const float* n1_w   = (const float*)d_in[1];
    const float* n1_b   = (const float*)d_in[2];
    const float* c1_w   = (const float*)d_in[3];
    const float* c1_b   = (const float*)d_in[4];
    const float* asn1_w = (const float*)d_in[5];
    const float* asn1_b = (const float*)d_in[6];
    const float* c21_w  = (const float*)d_in[7];
    const float* c21_b  = (const float*)d_in[8];
    const float* c22_w  = (const float*)d_in[9];
    const float* c22_b  = (const float*)d_in[10];
    const float* asn2_w = (const float*)d_in[11];
    const float* asn2_b = (const float*)d_in[12];
    const float* c3_w   = (const float*)d_in[13];
    const float* c3_b   = (const float*)d_in[14];
    const float* n2_w   = (const float*)d_in[15];
    const float* n2_b   = (const float*)d_in[16];
    const float* fc1_w  = (const float*)d_in[17];
    const float* fc1_b  = (const float*)d_in[18];
    const float* fc2_w  = (const float*)d_in[19];
    const float* fc2_b  = (const float*)d_in[20];
    float* out = (float*)d_out;

    float *bufA, *bufS, *bufX1;
    __half *pAh, *pAl, *lrh, *lrl, *tdh, *tdl, *hidh, *hidl, *wh;
    float2 *part, *stats;
    cudaGetSymbolAddress((void**)&bufA,  g_bufA);
    cudaGetSymbolAddress((void**)&bufS,  g_bufS);
    cudaGetSymbolAddress((void**)&bufX1, g_bufX1);
    cudaGetSymbolAddress((void**)&pAh,   g_pAh);
    cudaGetSymbolAddress((void**)&pAl,   g_pAl);
    cudaGetSymbolAddress((void**)&lrh,   g_lrh);
    cudaGetSymbolAddress((void**)&lrl,   g_lrl);
    cudaGetSymbolAddress((void**)&tdh,   g_tdh);
    cudaGetSymbolAddress((void**)&tdl,   g_tdl);
    cudaGetSymbolAddress((void**)&hidh,  g_hidh);
    cudaGetSymbolAddress((void**)&hidl,  g_hidl);
    cudaGetSymbolAddress((void**)&part,  g_part);
    cudaGetSymbolAddress((void**)&stats, g_stats);
    cudaGetSymbolAddress((void**)&wh,    g_wh);

    float2* st0 = stats + 0 * B_IMG;
    float2* st1 = stats + 1 * B_IMG;
    float2* st2 = stats + 2 * B_IMG;
    float2* st3 = stats + 3 * B_IMG;

    const int NWS = C_CH * C_CH, NWB = HID_CH * C_CH;
    const int O_C1 = 0, O_C21 = NWS, O_C22 = 2*NWS, O_C3 = 3*NWS,
              O_FC1 = 4*NWS, O_FC2 = 4*NWS + NWB;

    cudaFuncSetAttribute(gemm_k<OUT_RAW>,        cudaFuncAttributeMaxDynamicSharedMemorySize, SMEM_BYTES);
    cudaFuncSetAttribute(gemm_k<OUT_GELU>,       cudaFuncAttributeMaxDynamicSharedMemorySize, SMEM_BYTES);
    cudaFuncSetAttribute(gemm_k<OUT_GELU_ACC>,   cudaFuncAttributeMaxDynamicSharedMemorySize, SMEM_BYTES);
    cudaFuncSetAttribute(gemm_k<OUT_ADD_RES>,    cudaFuncAttributeMaxDynamicSharedMemorySize, SMEM_BYTES);
    cudaFuncSetAttribute(gemm_k<OUT_GELU_PACK2>, cudaFuncAttributeMaxDynamicSharedMemorySize, SMEM_BYTES);

    dim3 redGrid(B_IMG, NBLK_RED);
    dim3 g256 (NPIX / BM, C_CH  / BN);   // (392, 1)? no: (392, 2)
    dim3 g1024(NPIX / BM, HID_CH / BN);  // (392, 8)
    const int PK_BLKS = NELEM / 4 / 256; // 12544
    const int SH_BLKS = NELEM / 256;     // 50176

    // #1-#3, then #4 = c1 GEMM (ncu profiles launch 4)
    reduce_part_k<<<redGrid, 256>>>(x, part);
    finalize_k<<<1, 32>>>(part, st0);
    combo_pack_wconv_k<<<dim3(PK_BLKS, 2), 256>>>(x, st0, n1_w, n1_b, pAh, pAl,
                                                  c1_w, c21_w, c22_w, c3_w, fc1_w, fc2_w, wh);
    gemm_k<OUT_RAW><<<g256, 256, SMEM_BYTES>>>(
        pAh, pAl, wh + O_C1, c1_b, nullptr, bufA, nullptr, nullptr, C_CH, C_CH);

    reduce_part_k<<<redGrid, 256>>>(bufA, part);
    finalize_k<<<1, 32>>>(part, st1);
    pack_shift_k<<<SH_BLKS, 256>>>(bufA, st1, asn1_w, asn1_b, lrh, lrl, tdh, tdl);
    gemm_k<OUT_GELU><<<g256, 256, SMEM_BYTES>>>(
        lrh, lrl, wh + O_C21, c21_b, nullptr, bufS, nullptr, nullptr, C_CH, C_CH);
    gemm_k<OUT_GELU_ACC><<<g256, 256, SMEM_BYTES>>>(
        tdh, tdl, wh + O_C22, c22_b, nullptr, bufS, nullptr, nullptr, C_CH, C_CH);

    reduce_part_k<<<redGrid, 256>>>(bufS, part);
    finalize_k<<<1, 32>>>(part, st2);
    pack_gn_k<<<PK_BLKS, 256>>>(bufS, st2, asn2_w, asn2_b, pAh, pAl);
    gemm_k<OUT_ADD_RES><<<g256, 256, SMEM_BYTES>>>(
        pAh, pAl, wh + O_C3, c3_b, x, bufX1, nullptr, nullptr, C_CH, C_CH);

    reduce_part_k<<<redGrid, 256>>>(bufX1, part);
    finalize_k<<<1, 32>>>(part, st3);
    pack_gn_k<<<PK_BLKS, 256>>>(bufX1, st3, n2_w, n2_b, pAh, pAl);
    gemm_k<OUT_GELU_PACK2><<<g1024, 256, SMEM_BYTES>>>(
        pAh, pAl, wh + O_FC1, fc1_b, nullptr, nullptr, hidh, hidl, HID_CH, C_CH);
    gemm_k<OUT_ADD_RES><<<g256, 256, SMEM_BYTES>>>(
        hidh, hidl, wh + O_FC2, fc2_b, bufX1, out, nullptr, nullptr, C_CH, HID_CH);
}

// round 9
// speedup vs baseline: 1.5846x; 1.0987x over previous
#include <cuda_runtime.h>
#include <cuda_fp16.h>
#include <math.h>
#include <stdint.h>

// ---------------- problem constants ----------------
#define B_IMG   16
#define C_CH    256
#define HID_CH  1024
#define HW      3136
#define W_DIM   56
#define PER_B   (C_CH * HW)
#define NPIX    (B_IMG * HW)          // 50176
#define NBLK_RED 128
#define SEG_RED (PER_B / NBLK_RED)    // 6272
#define NELEM   (B_IMG * C_CH * HW)   // 12845056

// GEMM tile config: 3-stage cp.async pipeline
#define BM 128
#define BN 128
#define BK 32
#define AROW_B  272                    // 128 px * 2B + 16 pad  (k-major A rows)
#define ABUF_B  (BK * AROW_B)          // 8704
#define BROW_B  80                     // 32 k * 2B + 16 pad
#define BBUF_B  (BN * BROW_B)          // 10240
#define STAGE_B (2 * ABUF_B + BBUF_B)  // 27648
#define NSTAGE  3
#define OFF_AHI(s) ((s) * STAGE_B)
#define OFF_ALO(s) ((s) * STAGE_B + ABUF_B)
#define OFF_BW(s)  ((s) * STAGE_B + 2 * ABUF_B)
#define EP_STRIDE 132
#define SMEM_BYTES (NSTAGE * STAGE_B)  // 82944 (>= epilogue 67584)

// ---------------- scratch ----------------
__device__ float g_bufA[NELEM];
__device__ float g_bufS[NELEM];
__device__ float g_bufX1[NELEM];
__device__ __half g_pAh[NELEM];
__device__ __half g_pAl[NELEM];
__device__ __half g_lrh[NELEM];
__device__ __half g_lrl[NELEM];
__device__ __half g_tdh[NELEM];
__device__ __half g_tdl[NELEM];
__device__ __half g_hidh[B_IMG * HID_CH * HW];   // single plane (fc2 A)
__device__ float2 g_part[B_IMG * NBLK_RED];
__device__ float2 g_stats[4 * B_IMG];
#define WTOT (4*C_CH*C_CH + 2*HID_CH*C_CH)   // 786432
__device__ __half g_wh[WTOT];

__device__ __forceinline__ float gelu_f(float v) {
    return 0.5f * v * (1.0f + erff(v * 0.7071067811865476f));
}
__device__ __forceinline__ unsigned smem_u32(const void* p) {
    unsigned a;
    asm("{ .reg .u64 t; cvta.to.shared.u64 t, %1; cvt.u32.u64 %0, t; }" : "=r"(a) : "l"(p));
    return a;
}
#define LDSM_X4(r, addr) \
    asm volatile("ldmatrix.sync.aligned.m8n8.x4.shared.b16 {%0,%1,%2,%3}, [%4];" \
                 : "=r"((r)[0]), "=r"((r)[1]), "=r"((r)[2]), "=r"((r)[3]) : "r"(addr))
#define LDSM_X4_T(r, addr) \
    asm volatile("ldmatrix.sync.aligned.m8n8.x4.trans.shared.b16 {%0,%1,%2,%3}, [%4];" \
                 : "=r"((r)[0]), "=r"((r)[1]), "=r"((r)[2]), "=r"((r)[3]) : "r"(addr))
#define MMA_F16(d, a, b0, b1) \
    asm volatile("mma.sync.aligned.m16n8k16.row.col.f32.f16.f16.f32 " \
                 "{%0,%1,%2,%3}, {%4,%5,%6,%7}, {%8,%9}, {%0,%1,%2,%3};" \
                 : "+f"((d)[0]), "+f"((d)[1]), "+f"((d)[2]), "+f"((d)[3]) \
                 : "r"((a)[0]), "r"((a)[1]), "r"((a)[2]), "r"((a)[3]), "r"(b0), "r"(b1))
#define CP_ASYNC16(saddr, gptr) \
    asm volatile("cp.async.cg.shared.global [%0], [%1], 16;" :: "r"(saddr), "l"(gptr) : "memory")
#define CP_COMMIT() asm volatile("cp.async.commit_group;" ::: "memory")
#define CP_WAIT0()  asm volatile("cp.async.wait_group 0;" ::: "memory")
#define CP_WAIT1()  asm volatile("cp.async.wait_group 1;" ::: "memory")

// ---------------- GN reductions ----------------
__global__ void reduce_part_k(const float* __restrict__ src, float2* __restrict__ part) {
    int b = blockIdx.x, blk = blockIdx.y;
    const float4* p = (const float4*)(src + (size_t)b * PER_B + blk * SEG_RED);
    float s = 0.f, ss = 0.f;
    for (int i = threadIdx.x; i < SEG_RED / 4; i += 256) {
        float4 v = p[i];
        s  += v.x + v.y + v.z + v.w;
        ss += v.x*v.x + v.y*v.y + v.z*v.z + v.w*v.w;
    }
    __shared__ float sh1[256], sh2[256];
    int t = threadIdx.x;
    sh1[t] = s; sh2[t] = ss;
    __syncthreads();
    for (int st = 128; st > 0; st >>= 1) {
        if (t < st) { sh1[t] += sh1[t+st]; sh2[t] += sh2[t+st]; }
        __syncthreads();
    }
    if (t == 0) part[b * NBLK_RED + blk] = make_float2(sh1[0], sh2[0]);
}

__global__ void finalize_k(const float2* __restrict__ part, float2* __restrict__ stats) {
    int b = threadIdx.x;
    if (b >= B_IMG) return;
    float s = 0.f, ss = 0.f;
    for (int i = 0; i < NBLK_RED; i++) {
        float2 p = part[b * NBLK_RED + i];
        s += p.x; ss += p.y;
    }
    const float n = (float)PER_B;
    float mean = s / n;
    float var  = ss / n - mean * mean;
    stats[b] = make_float2(mean, rsqrtf(var + 1e-5f));
}

// ---------------- pack bodies ----------------
__device__ __forceinline__ void pack_gn_body(const float* __restrict__ src,
                                             const float2* __restrict__ stats,
                                             const float* __restrict__ gamma,
                                             const float* __restrict__ beta,
                                             __half* __restrict__ dhi, __half* __restrict__ dlo,
                                             int i4) {
    int i = i4 * 4;
    int b = i / PER_B;
    int r = i - b * PER_B;
    int c = r / HW;
    float2 st = stats[b];
    float g = gamma[c], be = beta[c];
    float4 v = ((const float4*)src)[i4];
    float f0 = (v.x - st.x) * st.y * g + be;
    float f1 = (v.y - st.x) * st.y * g + be;
    float f2 = (v.z - st.x) * st.y * g + be;
    float f3 = (v.w - st.x) * st.y * g + be;
    __half h0 = __float2half_rn(f0), h1 = __float2half_rn(f1);
    __half h2 = __float2half_rn(f2), h3 = __float2half_rn(f3);
    ((ushort4*)dhi)[i4] = make_ushort4(__half_as_ushort(h0), __half_as_ushort(h1),
                                       __half_as_ushort(h2), __half_as_ushort(h3));
    __half l0 = __float2half_rn(f0 - __half2float(h0));
    __half l1 = __float2half_rn(f1 - __half2float(h1));
    __half l2 = __float2half_rn(f2 - __half2float(h2));
    __half l3 = __float2half_rn(f3 - __half2float(h3));
    ((ushort4*)dlo)[i4] = make_ushort4(__half_as_ushort(l0), __half_as_ushort(l1),
                                       __half_as_ushort(l2), __half_as_ushort(l3));
}

__global__ void pack_gn_k(const float* __restrict__ src, const float2* __restrict__ stats,
                          const float* __restrict__ gamma, const float* __restrict__ beta,
                          __half* __restrict__ dhi, __half* __restrict__ dlo) {
    int i4 = blockIdx.x * 256 + threadIdx.x;
    if (i4 < NELEM / 4) pack_gn_body(src, stats, gamma, beta, dhi, dlo, i4);
}

// combo: y=0 -> pack_gn(x); y=1 -> weight fp16 conversion
__global__ void combo_pack_wconv_k(const float* __restrict__ x, const float2* __restrict__ stats,
                                   const float* __restrict__ gamma, const float* __restrict__ beta,
                                   __half* __restrict__ dhi, __half* __restrict__ dlo,
                                   const float* w0, const float* w1, const float* w2,
                                   const float* w3, const float* w4, const float* w5,
                                   __half* __restrict__ wdst) {
    if (blockIdx.y == 0) {
        int i4 = blockIdx.x * 256 + threadIdx.x;
        if (i4 < NELEM / 4) pack_gn_body(x, stats, gamma, beta, dhi, dlo, i4);
    } else {
        int i = blockIdx.x * 256 + threadIdx.x;
        if (i < 262144) {
            const float* srcs[4] = { w0, w1, w2, w3 };
            wdst[i] = __float2half_rn(srcs[i >> 16][i & 65535]);
        } else if (i < 524288) {
            wdst[i] = __float2half_rn(w4[i - 262144]);
        } else if (i < 786432) {
            wdst[i] = __float2half_rn(w5[i - 524288]);
        }
    }
}

// shift pre-pass: lr/td planes = gelu(GN(bufA)) shifted, zero-filled
__global__ void pack_shift_k(const float* __restrict__ src, const float2* __restrict__ stats,
                             const float* __restrict__ gamma, const float* __restrict__ beta,
                             __half* __restrict__ lrh, __half* __restrict__ lrl,
                             __half* __restrict__ tdh, __half* __restrict__ tdl) {
    int idx = blockIdx.x * 256 + threadIdx.x;
    if (idx >= NELEM) return;
    int b = idx / PER_B;
    int r = idx - b * PER_B;
    int c = r / HW;
    int hw = r - c * HW;
    int h = hw / W_DIM, w = hw - h * W_DIM;
    float2 st = stats[b];
    float g = gamma[c], be = beta[c];
    int s = 3 - c / 37;                 // group = ceil(256/7) = 37
    const float* base = src + (size_t)(b * C_CH + c) * HW;
    float vlr = 0.f, vtd = 0.f;
    int w2 = w + s;
    if (w2 >= 0 && w2 < W_DIM)
        vlr = gelu_f((base[h * W_DIM + w2] - st.x) * st.y * g + be);
    int h2 = h + s;
    if (h2 >= 0 && h2 < W_DIM)
        vtd = gelu_f((base[h2 * W_DIM + w] - st.x) * st.y * g + be);
    __half a = __float2half_rn(vlr);
    lrh[idx] = a;
    lrl[idx] = __float2half_rn(vlr - __half2float(a));
    __half d = __float2half_rn(vtd);
    tdh[idx] = d;
    tdl[idx] = __float2half_rn(vtd - __half2float(d));
}

// ---------------- pure cp.async HMMA GEMM (3-stage) ----------------
#define OUT_RAW        0
#define OUT_GELU       1
#define OUT_GELU_ACC   2
#define OUT_ADD_RES    3
#define OUT_GELU_PACKH 4   // write single fp16 plane of gelu(v)

template<int OM, int NA>
__global__ void __launch_bounds__(256, 2) gemm_k(
    const __half* __restrict__ Ahi, const __half* __restrict__ Alo,
    const __half* __restrict__ W,
    const float* __restrict__ bias, const float* __restrict__ res,
    float* __restrict__ out, __half* __restrict__ o2h,
    int Mout, int K)
{
    extern __shared__ char smem[];
    const unsigned sb = smem_u32(smem);

    const int tid  = threadIdx.x;
    const int wid  = tid >> 5;
    const int lane = tid & 31;
    const int warp_m = wid & 3;
    const int warp_n = wid >> 2;
    const int n0 = blockIdx.y * BN;
    const int nch = K / BK;

    // A cp.async mapping: 2 slots/thread per plane
    const int ak0 = tid >> 4,         ab0 = tid & 15;
    const int ak1 = (tid + 256) >> 4, ab1 = (tid + 256) & 15;
    int gp0 = blockIdx.x * BM + ab0 * 8;
    int bb0 = gp0 / HW;
    size_t abase0 = (size_t)bb0 * K * HW + (gp0 - bb0 * HW);
    int gp1 = blockIdx.x * BM + ab1 * 8;
    int bb1 = gp1 / HW;
    size_t abase1 = (size_t)bb1 * K * HW + (gp1 - bb1 * HW);
    const unsigned as0 = ak0 * AROW_B + ab0 * 16;
    const unsigned as1 = ak1 * AROW_B + ab1 * 16;
    // B mapping
    const int brow0 = tid >> 2,         bq0 = tid & 3;
    const int brow1 = (tid + 256) >> 2, bq1 = (tid + 256) & 3;
    const unsigned bso0 = brow0 * BROW_B + bq0 * 16;
    const unsigned bso1 = brow1 * BROW_B + bq1 * 16;
    const size_t wrow0 = (size_t)(n0 + brow0) * K;
    const size_t wrow1 = (size_t)(n0 + brow1) * K;

    float acc[2][8][4];
    #pragma unroll
    for (int i = 0; i < 2; i++)
        #pragma unroll
        for (int j = 0; j < 8; j++)
            #pragma unroll
            for (int q = 0; q < 4; q++) acc[i][j][q] = 0.f;

    const unsigned a_klane = ((lane >> 4) & 1) * 8 + (lane & 7);
    const unsigned a_mcolB = (warp_m * 32 + ((lane >> 3) & 1) * 8) * 2;
    const unsigned b_lrow  = warp_n * 64 + ((lane & 16) >> 1) + (lane & 7);
    const unsigned b_lcolB = ((lane >> 3) & 1) * 16;

    // prologue: stages 0, 1
    #pragma unroll
    for (int s = 0; s < 2; ++s) {
        const int kk = s * BK;
        CP_ASYNC16(sb + OFF_AHI(s) + as0, Ahi + abase0 + (size_t)(kk + ak0) * HW);
        CP_ASYNC16(sb + OFF_AHI(s) + as1, Ahi + abase1 + (size_t)(kk + ak1) * HW);
        if (NA == 2) {
            CP_ASYNC16(sb + OFF_ALO(s) + as0, Alo + abase0 + (size_t)(kk + ak0) * HW);
            CP_ASYNC16(sb + OFF_ALO(s) + as1, Alo + abase1 + (size_t)(kk + ak1) * HW);
        }
        CP_ASYNC16(sb + OFF_BW(s) + bso0, W + wrow0 + kk + bq0 * 8);
        CP_ASYNC16(sb + OFF_BW(s) + bso1, W + wrow1 + kk + bq1 * 8);
        CP_COMMIT();
    }
    CP_WAIT1();
    __syncthreads();

    int stage = 0;
    for (int i = 0; i < nch; ++i) {
        const bool pre = (i + 2 < nch);
        if (pre) {
            int sN = stage + 2; if (sN >= NSTAGE) sN -= NSTAGE;
            const int kk = (i + 2) * BK;
            CP_ASYNC16(sb + OFF_AHI(sN) + as0, Ahi + abase0 + (size_t)(kk + ak0) * HW);
            CP_ASYNC16(sb + OFF_AHI(sN) + as1, Ahi + abase1 + (size_t)(kk + ak1) * HW);
            if (NA == 2) {
                CP_ASYNC16(sb + OFF_ALO(sN) + as0, Alo + abase0 + (size_t)(kk + ak0) * HW);
                CP_ASYNC16(sb + OFF_ALO(sN) + as1, Alo + abase1 + (size_t)(kk + ak1) * HW);
            }
            CP_ASYNC16(sb + OFF_BW(sN) + bso0, W + wrow0 + kk + bq0 * 8);
            CP_ASYNC16(sb + OFF_BW(sN) + bso1, W + wrow1 + kk + bq1 * 8);
            CP_COMMIT();
        }

        const unsigned Ah = sb + OFF_AHI(stage), Al = sb + OFF_ALO(stage), Bb = sb + OFF_BW(stage);
        #pragma unroll
        for (int ks = 0; ks < 2; ++ks) {
            unsigned ahf[2][4], alf[2][4];
            #pragma unroll
            for (int mi = 0; mi < 2; ++mi) {
                unsigned off = (ks * 16 + a_klane) * AROW_B + a_mcolB + mi * 32;
                LDSM_X4_T(ahf[mi], Ah + off);
                if (NA == 2) LDSM_X4_T(alf[mi], Al + off);
            }
            #pragma unroll
            for (int nip = 0; nip < 4; ++nip) {
                unsigned bf[4];
                unsigned off = (b_lrow + nip * 16) * BROW_B + ks * 32 + b_lcolB;
                LDSM_X4(bf, Bb + off);
                #pragma unroll
                for (int mi = 0; mi < 2; ++mi) {
                    #pragma unroll
                    for (int h = 0; h < 2; ++h) {
                        float* d = acc[mi][nip * 2 + h];
                        MMA_F16(d, ahf[mi], bf[2*h], bf[2*h+1]);
                        if (NA == 2) MMA_F16(d, alf[mi], bf[2*h], bf[2*h+1]);
                    }
                }
            }
        }

        if (pre) CP_WAIT1(); else CP_WAIT0();
        __syncthreads();
        stage = (stage + 1 == NSTAGE) ? 0 : stage + 1;
    }

    // epilogue via smem transpose
    float* ep = (float*)smem;
    const int r4 = lane >> 2;
    const int c2 = (lane & 3) * 2;
    #pragma unroll
    for (int mi = 0; mi < 2; ++mi) {
        #pragma unroll
        for (int ni = 0; ni < 8; ++ni) {
            int m = warp_m * 32 + mi * 16 + r4;
            int n = warp_n * 64 + ni * 8 + c2;
            ep[n * EP_STRIDE + m]           = acc[mi][ni][0];
            ep[(n + 1) * EP_STRIDE + m]     = acc[mi][ni][1];
            ep[n * EP_STRIDE + m + 8]       = acc[mi][ni][2];
            ep[(n + 1) * EP_STRIDE + m + 8] = acc[mi][ni][3];
        }
    }
    __syncthreads();

    #pragma unroll 4
    for (int it = 0; it < 64; ++it) {
        int flat = it * 256 + tid;
        int nl = flat >> 7;
        int m  = flat & 127;
        int g  = blockIdx.x * BM + m;
        int be = g / HW;
        int hwe = g - be * HW;
        int n  = n0 + nl;
        float v = ep[nl * EP_STRIDE + m] + bias[n];
        size_t idx = ((size_t)be * Mout + n) * HW + hwe;
        if (OM == OUT_RAW)            out[idx] = v;
        else if (OM == OUT_GELU)      out[idx] = gelu_f(v);
        else if (OM == OUT_GELU_ACC)  out[idx] += gelu_f(v);
        else if (OM == OUT_ADD_RES)   out[idx] = v + res[idx];
        else                          o2h[idx] = __float2half_rn(gelu_f(v));
    }
}

// ---------------- launch ----------------
extern "C" void kernel_launch(void* const* d_in, const int* in_sizes, int n_in,
                              void* d_out, int out_size)
{
    const float* x      = (const float*)d_in[0];
    const float* n1_w   = (const float*)d_in[1];
    const float* n1_b   = (const float*)d_in[2];
    const float* c1_w   = (const float*)d_in[3];
    const float* c1_b   = (const float*)d_in[4];
    const float* asn1_w = (const float*)d_in[5];
    const float* asn1_b = (const float*)d_in[6];
    const float* c21_w  = (const float*)d_in[7];
    const float* c21_b  = (const float*)d_in[8];
    const float* c22_w  = (const float*)d_in[9];
    const float* c22_b  = (const float*)d_in[10];
    const float* asn2_w = (const float*)d_in[11];
    const float* asn2_b = (const float*)d_in[12];
    const float* c3_w   = (const float*)d_in[13];
    const float* c3_b   = (const float*)d_in[14];
    const float* n2_w   = (const float*)d_in[15];
    const float* n2_b   = (const float*)d_in[16];
    const float* fc1_w  = (const float*)d_in[17];
    const float* fc1_b  = (const float*)d_in[18];
    const float* fc2_w  = (const float*)d_in[19];
    const float* fc2_b  = (const float*)d_in[20];
    float* out = (float*)d_out;

    float *bufA, *bufS, *bufX1;
    __half *pAh, *pAl, *lrh, *lrl, *tdh, *tdl, *hidh, *wh;
    float2 *part, *stats;
    cudaGetSymbolAddress((void**)&bufA,  g_bufA);
    cudaGetSymbolAddress((void**)&bufS,  g_bufS);
    cudaGetSymbolAddress((void**)&bufX1, g_bufX1);
    cudaGetSymbolAddress((void**)&pAh,   g_pAh);
    cudaGetSymbolAddress((void**)&pAl,   g_pAl);
    cudaGetSymbolAddress((void**)&lrh,   g_lrh);
    cudaGetSymbolAddress((void**)&lrl,   g_lrl);
    cudaGetSymbolAddress((void**)&tdh,   g_tdh);
    cudaGetSymbolAddress((void**)&tdl,   g_tdl);
    cudaGetSymbolAddress((void**)&hidh,  g_hidh);
    cudaGetSymbolAddress((void**)&part,  g_part);
    cudaGetSymbolAddress((void**)&stats, g_stats);
    cudaGetSymbolAddress((void**)&wh,    g_wh);

    float2* st0 = stats + 0 * B_IMG;
    float2* st1 = stats + 1 * B_IMG;
    float2* st2 = stats + 2 * B_IMG;
    float2* st3 = stats + 3 * B_IMG;

    const int NWS = C_CH * C_CH, NWB = HID_CH * C_CH;
    const int O_C1 = 0, O_C21 = NWS, O_C22 = 2*NWS, O_C3 = 3*NWS,
              O_FC1 = 4*NWS, O_FC2 = 4*NWS + NWB;

    cudaFuncSetAttribute(gemm_k<OUT_RAW, 2>,        cudaFuncAttributeMaxDynamicSharedMemorySize, SMEM_BYTES);
    cudaFuncSetAttribute(gemm_k<OUT_GELU, 2>,       cudaFuncAttributeMaxDynamicSharedMemorySize, SMEM_BYTES);
    cudaFuncSetAttribute(gemm_k<OUT_GELU_ACC, 2>,   cudaFuncAttributeMaxDynamicSharedMemorySize, SMEM_BYTES);
    cudaFuncSetAttribute(gemm_k<OUT_ADD_RES, 2>,    cudaFuncAttributeMaxDynamicSharedMemorySize, SMEM_BYTES);
    cudaFuncSetAttribute(gemm_k<OUT_GELU_PACKH, 2>, cudaFuncAttributeMaxDynamicSharedMemorySize, SMEM_BYTES);
    cudaFuncSetAttribute(gemm_k<OUT_ADD_RES, 1>,    cudaFuncAttributeMaxDynamicSharedMemorySize, SMEM_BYTES);

    dim3 redGrid(B_IMG, NBLK_RED);
    dim3 g256 (NPIX / BM, C_CH  / BN);   // (392, 2)
    dim3 g1024(NPIX / BM, HID_CH / BN);  // (392, 8)
    const int PK_BLKS = NELEM / 4 / 256;
    const int SH_BLKS = NELEM / 256;

    // #1-#3, then #4 = c1 GEMM (ncu profiles launch 4)
    reduce_part_k<<<redGrid, 256>>>(x, part);
    finalize_k<<<1, 32>>>(part, st0);
    combo_pack_wconv_k<<<dim3(PK_BLKS, 2), 256>>>(x, st0, n1_w, n1_b, pAh, pAl,
                                                  c1_w, c21_w, c22_w, c3_w, fc1_w, fc2_w, wh);
    gemm_k<OUT_RAW, 2><<<g256, 256, SMEM_BYTES>>>(
        pAh, pAl, wh + O_C1, c1_b, nullptr, bufA, nullptr, C_CH, C_CH);

    reduce_part_k<<<redGrid, 256>>>(bufA, part);
    finalize_k<<<1, 32>>>(part, st1);
    pack_shift_k<<<SH_BLKS, 256>>>(bufA, st1, asn1_w, asn1_b, lrh, lrl, tdh, tdl);
    gemm_k<OUT_GELU, 2><<<g256, 256, SMEM_BYTES>>>(
        lrh, lrl, wh + O_C21, c21_b, nullptr, bufS, nullptr, C_CH, C_CH);
    gemm_k<OUT_GELU_ACC, 2><<<g256, 256, SMEM_BYTES>>>(
        tdh, tdl, wh + O_C22, c22_b, nullptr, bufS, nullptr, C_CH, C_CH);

    reduce_part_k<<<redGrid, 256>>>(bufS, part);
    finalize_k<<<1, 32>>>(part, st2);
    pack_gn_k<<<PK_BLKS, 256>>>(bufS, st2, asn2_w, asn2_b, pAh, pAl);
    gemm_k<OUT_ADD_RES, 2><<<g256, 256, SMEM_BYTES>>>(
        pAh, pAl, wh + O_C3, c3_b, x, bufX1, nullptr, C_CH, C_CH);

    reduce_part_k<<<redGrid, 256>>>(bufX1, part);
    finalize_k<<<1, 32>>>(part, st3);
    pack_gn_k<<<PK_BLKS, 256>>>(bufX1, st3, n2_w, n2_b, pAh, pAl);
    gemm_k<OUT_GELU_PACKH, 2><<<g1024, 256, SMEM_BYTES>>>(
        pAh, pAl, wh + O_FC1, fc1_b, nullptr, nullptr, hidh, HID_CH, C_CH);
    gemm_k<OUT_ADD_RES, 1><<<g256, 256, SMEM_BYTES>>>(
        hidh, nullptr, wh + O_FC2, fc2_b, bufX1, out, nullptr, C_CH, HID_CH);
}

// round 10
// speedup vs baseline: 1.6764x; 1.0579x over previous
#include <cuda_runtime.h>
#include <cuda_fp16.h>
#include <math.h>
#include <stdint.h>

// ---------------- problem constants ----------------
#define B_IMG   16
#define C_CH    256
#define HID_CH  1024
#define HW      3136
#define W_DIM   56
#define PER_B   (C_CH * HW)
#define NPIX    (B_IMG * HW)          // 50176
#define NBLK_RED 128
#define SEG_RED (PER_B / NBLK_RED)    // 6272
#define NELEM   (B_IMG * C_CH * HW)   // 12845056

// GEMM tile config: 2-stage cp.async pipeline, BK=64
#define BM 128
#define BN 128
#define BK 64
#define AROW_B  272                    // 128 px * 2B + 16 pad  (k-major A rows)
#define ABUF_B  (BK * AROW_B)          // 17408 per plane
#define BROW_B  80                     // 32 k * 2B + 16 pad (per sub-buffer)
#define BSUB_B  (BN * BROW_B)          // 10240
#define BBUF_B  (2 * BSUB_B)           // 20480 (two 32-k halves)
#define STAGE_B (2 * ABUF_B + BBUF_B)  // 55296
#define NSTAGE  2
#define OFF_AHI(s) ((s) * STAGE_B)
#define OFF_ALO(s) ((s) * STAGE_B + ABUF_B)
#define OFF_BW(s)  ((s) * STAGE_B + 2 * ABUF_B)
#define EP_STRIDE 132
#define SMEM_BYTES (NSTAGE * STAGE_B)  // 110592 (>= epilogue 67584)

// ---------------- scratch ----------------
__device__ float g_bufA[NELEM];
__device__ float g_bufS[NELEM];
__device__ float g_bufX1[NELEM];
__device__ __half g_pAh[NELEM];
__device__ __half g_pAl[NELEM];
__device__ __half g_lrh[NELEM];
__device__ __half g_lrl[NELEM];
__device__ __half g_tdh[NELEM];
__device__ __half g_tdl[NELEM];
__device__ __half g_hidh[B_IMG * HID_CH * HW];   // single plane (fc2 A)
__device__ float2 g_part[B_IMG * NBLK_RED];
__device__ float2 g_stats[4 * B_IMG];
#define WTOT (4*C_CH*C_CH + 2*HID_CH*C_CH)   // 786432
__device__ __half g_wh[WTOT];

__device__ __forceinline__ float gelu_f(float v) {
    return 0.5f * v * (1.0f + erff(v * 0.7071067811865476f));
}
__device__ __forceinline__ unsigned smem_u32(const void* p) {
    unsigned a;
    asm("{ .reg .u64 t; cvta.to.shared.u64 t, %1; cvt.u32.u64 %0, t; }" : "=r"(a) : "l"(p));
    return a;
}
#define LDSM_X4(r, addr) \
    asm volatile("ldmatrix.sync.aligned.m8n8.x4.shared.b16 {%0,%1,%2,%3}, [%4];" \
                 : "=r"((r)[0]), "=r"((r)[1]), "=r"((r)[2]), "=r"((r)[3]) : "r"(addr))
#define LDSM_X4_T(r, addr) \
    asm volatile("ldmatrix.sync.aligned.m8n8.x4.trans.shared.b16 {%0,%1,%2,%3}, [%4];" \
                 : "=r"((r)[0]), "=r"((r)[1]), "=r"((r)[2]), "=r"((r)[3]) : "r"(addr))
#define MMA_F16(d, a, b0, b1) \
    asm volatile("mma.sync.aligned.m16n8k16.row.col.f32.f16.f16.f32 " \
                 "{%0,%1,%2,%3}, {%4,%5,%6,%7}, {%8,%9}, {%0,%1,%2,%3};" \
                 : "+f"((d)[0]), "+f"((d)[1]), "+f"((d)[2]), "+f"((d)[3]) \
                 : "r"((a)[0]), "r"((a)[1]), "r"((a)[2]), "r"((a)[3]), "r"(b0), "r"(b1))
#define CP_ASYNC16(saddr, gptr) \
    asm volatile("cp.async.cg.shared.global [%0], [%1], 16;" :: "r"(saddr), "l"(gptr) : "memory")
#define CP_COMMIT() asm volatile("cp.async.commit_group;" ::: "memory")
#define CP_WAIT0()  asm volatile("cp.async.wait_group 0;" ::: "memory")
#define CP_WAIT1()  asm volatile("cp.async.wait_group 1;" ::: "memory")

// ---------------- GN reductions ----------------
__global__ void reduce_part_k(const float* __restrict__ src, float2* __restrict__ part) {
    int b = blockIdx.x, blk = blockIdx.y;
    const float4* p = (const float4*)(src + (size_t)b * PER_B + blk * SEG_RED);
    float s = 0.f, ss = 0.f;
    for (int i = threadIdx.x; i < SEG_RED / 4; i += 256) {
        float4 v = p[i];
        s  += v.x + v.y + v.z + v.w;
        ss += v.x*v.x + v.y*v.y + v.z*v.z + v.w*v.w;
    }
    __shared__ float sh1[256], sh2[256];
    int t = threadIdx.x;
    sh1[t] = s; sh2[t] = ss;
    __syncthreads();
    for (int st = 128; st > 0; st >>= 1) {
        if (t < st) { sh1[t] += sh1[t+st]; sh2[t] += sh2[t+st]; }
        __syncthreads();
    }
    if (t == 0) part[b * NBLK_RED + blk] = make_float2(sh1[0], sh2[0]);
}

__global__ void finalize_k(const float2* __restrict__ part, float2* __restrict__ stats) {
    int b = threadIdx.x;
    if (b >= B_IMG) return;
    float s = 0.f, ss = 0.f;
    for (int i = 0; i < NBLK_RED; i++) {
        float2 p = part[b * NBLK_RED + i];
        s += p.x; ss += p.y;
    }
    const float n = (float)PER_B;
    float mean = s / n;
    float var  = ss / n - mean * mean;
    stats[b] = make_float2(mean, rsqrtf(var + 1e-5f));
}

// ---------------- pack bodies ----------------
__device__ __forceinline__ void pack_gn_body(const float* __restrict__ src,
                                             const float2* __restrict__ stats,
                                             const float* __restrict__ gamma,
                                             const float* __restrict__ beta,
                                             __half* __restrict__ dhi, __half* __restrict__ dlo,
                                             int i4) {
    int i = i4 * 4;
    int b = i / PER_B;
    int r = i - b * PER_B;
    int c = r / HW;
    float2 st = stats[b];
    float g = gamma[c], be = beta[c];
    float4 v = ((const float4*)src)[i4];
    float f0 = (v.x - st.x) * st.y * g + be;
    float f1 = (v.y - st.x) * st.y * g + be;
    float f2 = (v.z - st.x) * st.y * g + be;
    float f3 = (v.w - st.x) * st.y * g + be;
    __half h0 = __float2half_rn(f0), h1 = __float2half_rn(f1);
    __half h2 = __float2half_rn(f2), h3 = __float2half_rn(f3);
    ((ushort4*)dhi)[i4] = make_ushort4(__half_as_ushort(h0), __half_as_ushort(h1),
                                       __half_as_ushort(h2), __half_as_ushort(h3));
    __half l0 = __float2half_rn(f0 - __half2float(h0));
    __half l1 = __float2half_rn(f1 - __half2float(h1));
    __half l2 = __float2half_rn(f2 - __half2float(h2));
    __half l3 = __float2half_rn(f3 - __half2float(h3));
    ((ushort4*)dlo)[i4] = make_ushort4(__half_as_ushort(l0), __half_as_ushort(l1),
                                       __half_as_ushort(l2), __half_as_ushort(l3));
}

__global__ void pack_gn_k(const float* __restrict__ src, const float2* __restrict__ stats,
                          const float* __restrict__ gamma, const float* __restrict__ beta,
                          __half* __restrict__ dhi, __half* __restrict__ dlo) {
    int i4 = blockIdx.x * 256 + threadIdx.x;
    if (i4 < NELEM / 4) pack_gn_body(src, stats, gamma, beta, dhi, dlo, i4);
}

// combo: y=0 -> pack_gn(x); y=1 -> weight fp16 conversion
__global__ void combo_pack_wconv_k(const float* __restrict__ x, const float2* __restrict__ stats,
                                   const float* __restrict__ gamma, const float* __restrict__ beta,
                                   __half* __restrict__ dhi, __half* __restrict__ dlo,
                                   const float* w0, const float* w1, const float* w2,
                                   const float* w3, const float* w4, const float* w5,
                                   __half* __restrict__ wdst) {
    if (blockIdx.y == 0) {
        int i4 = blockIdx.x * 256 + threadIdx.x;
        if (i4 < NELEM / 4) pack_gn_body(x, stats, gamma, beta, dhi, dlo, i4);
    } else {
        int i = blockIdx.x * 256 + threadIdx.x;
        if (i < 262144) {
            const float* srcs[4] = { w0, w1, w2, w3 };
            wdst[i] = __float2half_rn(srcs[i >> 16][i & 65535]);
        } else if (i < 524288) {
            wdst[i] = __float2half_rn(w4[i - 262144]);
        } else if (i < 786432) {
            wdst[i] = __float2half_rn(w5[i - 524288]);
        }
    }
}

// shift pre-pass: lr/td planes = gelu(GN(bufA)) shifted, zero-filled
__global__ void pack_shift_k(const float* __restrict__ src, const float2* __restrict__ stats,
                             const float* __restrict__ gamma, const float* __restrict__ beta,
                             __half* __restrict__ lrh, __half* __restrict__ lrl,
                             __half* __restrict__ tdh, __half* __restrict__ tdl) {
    int idx = blockIdx.x * 256 + threadIdx.x;
    if (idx >= NELEM) return;
    int b = idx / PER_B;
    int r = idx - b * PER_B;
    int c = r / HW;
    int hw = r - c * HW;
    int h = hw / W_DIM, w = hw - h * W_DIM;
    float2 st = stats[b];
    float g = gamma[c], be = beta[c];
    int s = 3 - c / 37;                 // group = ceil(256/7) = 37
    const float* base = src + (size_t)(b * C_CH + c) * HW;
    float vlr = 0.f, vtd = 0.f;
    int w2 = w + s;
    if (w2 >= 0 && w2 < W_DIM)
        vlr = gelu_f((base[h * W_DIM + w2] - st.x) * st.y * g + be);
    int h2 = h + s;
    if (h2 >= 0 && h2 < W_DIM)
        vtd = gelu_f((base[h2 * W_DIM + w] - st.x) * st.y * g + be);
    __half a = __float2half_rn(vlr);
    lrh[idx] = a;
    lrl[idx] = __float2half_rn(vlr - __half2float(a));
    __half d = __float2half_rn(vtd);
    tdh[idx] = d;
    tdl[idx] = __float2half_rn(vtd - __half2float(d));
}

// ---------------- pure cp.async HMMA GEMM (2-stage, BK=64) ----------------
#define OUT_RAW        0
#define OUT_GELU       1
#define OUT_GELU_ACC   2
#define OUT_ADD_RES    3
#define OUT_GELU_PACKH 4   // write single fp16 plane of gelu(v)

template<int OM, int NA>
__global__ void __launch_bounds__(256, 2) gemm_k(
    const __half* __restrict__ Ahi, const __half* __restrict__ Alo,
    const __half* __restrict__ W,
    const float* __restrict__ bias, const float* __restrict__ res,
    float* __restrict__ out, __half* __restrict__ o2h,
    int Mout, int K)
{
    extern __shared__ char smem[];
    const unsigned sb = smem_u32(smem);

    const int tid  = threadIdx.x;
    const int wid  = tid >> 5;
    const int lane = tid & 31;
    const int warp_m = wid & 3;
    const int warp_n = wid >> 2;
    const int n0 = blockIdx.y * BN;
    const int nch = K / BK;

    // A cp.async mapping: 4 slots/thread per plane (slot = tid + 256r, r=0..3)
    // slot -> k = slot>>4 (0..63), px-block = slot&15
    int aks[4], abs_[4];
    size_t abase[4];
    unsigned asoff[4];
    #pragma unroll
    for (int r = 0; r < 4; ++r) {
        int slot = tid + 256 * r;
        aks[r]  = slot >> 4;
        abs_[r] = slot & 15;
        int gp = blockIdx.x * BM + abs_[r] * 8;
        int bb = gp / HW;
        abase[r] = (size_t)bb * K * HW + (gp - bb * HW);
        asoff[r] = aks[r] * AROW_B + abs_[r] * 16;
    }
    // B mapping: rows brow0(0..63), brow1(64..127), two 32-k sub-buffers
    const int brow0 = tid >> 2,         bq0 = tid & 3;
    const int brow1 = (tid + 256) >> 2, bq1 = (tid + 256) & 3;
    const size_t wrow0 = (size_t)(n0 + brow0) * K;
    const size_t wrow1 = (size_t)(n0 + brow1) * K;
    const unsigned bso0 = brow0 * BROW_B + bq0 * 16;
    const unsigned bso1 = brow1 * BROW_B + bq1 * 16;

    float acc[2][8][4];
    #pragma unroll
    for (int i = 0; i < 2; i++)
        #pragma unroll
        for (int j = 0; j < 8; j++)
            #pragma unroll
            for (int q = 0; q < 4; q++) acc[i][j][q] = 0.f;

    const unsigned a_klane = ((lane >> 4) & 1) * 8 + (lane & 7);
    const unsigned a_mcolB = (warp_m * 32 + ((lane >> 3) & 1) * 8) * 2;
    const unsigned b_lrow  = warp_n * 64 + ((lane & 16) >> 1) + (lane & 7);
    const unsigned b_lcolB = ((lane >> 3) & 1) * 16;

    // prologue: stage 0 (chunk 0)
    {
        #pragma unroll
        for (int r = 0; r < 4; ++r)
            CP_ASYNC16(sb + OFF_AHI(0) + asoff[r], Ahi + abase[r] + (size_t)aks[r] * HW);
        if (NA == 2)
            #pragma unroll
            for (int r = 0; r < 4; ++r)
                CP_ASYNC16(sb + OFF_ALO(0) + asoff[r], Alo + abase[r] + (size_t)aks[r] * HW);
        #pragma unroll
        for (int sub = 0; sub < 2; ++sub) {
            CP_ASYNC16(sb + OFF_BW(0) + sub * BSUB_B + bso0, W + wrow0 + sub * 32 + bq0 * 8);
            CP_ASYNC16(sb + OFF_BW(0) + sub * BSUB_B + bso1, W + wrow1 + sub * 32 + bq1 * 8);
        }
        CP_COMMIT();
        CP_WAIT0();
        __syncthreads();
    }

    for (int i = 0; i < nch; ++i) {
        const int cur = i & 1;
        const bool pre = (i + 1 < nch);
        if (pre) {
            const int nxt = cur ^ 1;
            const int kk = (i + 1) * BK;
            #pragma unroll
            for (int r = 0; r < 4; ++r)
                CP_ASYNC16(sb + OFF_AHI(nxt) + asoff[r], Ahi + abase[r] + (size_t)(kk + aks[r]) * HW);
            if (NA == 2)
                #pragma unroll
                for (int r = 0; r < 4; ++r)
                    CP_ASYNC16(sb + OFF_ALO(nxt) + asoff[r], Alo + abase[r] + (size_t)(kk + aks[r]) * HW);
            #pragma unroll
            for (int sub = 0; sub < 2; ++sub) {
                CP_ASYNC16(sb + OFF_BW(nxt) + sub * BSUB_B + bso0, W + wrow0 + kk + sub * 32 + bq0 * 8);
                CP_ASYNC16(sb + OFF_BW(nxt) + sub * BSUB_B + bso1, W + wrow1 + kk + sub * 32 + bq1 * 8);
            }
            CP_COMMIT();
        }

        const unsigned Ah = sb + OFF_AHI(cur), Al = sb + OFF_ALO(cur), Bb = sb + OFF_BW(cur);
        #pragma unroll
        for (int ks = 0; ks < 4; ++ks) {
            unsigned ahf[2][4], alf[2][4];
            #pragma unroll
            for (int mi = 0; mi < 2; ++mi) {
                unsigned off = (ks * 16 + a_klane) * AROW_B + a_mcolB + mi * 32;
                LDSM_X4_T(ahf[mi], Ah + off);
                if (NA == 2) LDSM_X4_T(alf[mi], Al + off);
            }
            #pragma unroll
            for (int nip = 0; nip < 4; ++nip) {
                unsigned bf[4];
                unsigned off = (ks >> 1) * BSUB_B + (b_lrow + nip * 16) * BROW_B
                             + (ks & 1) * 32 + b_lcolB;
                LDSM_X4(bf, Bb + off);
                #pragma unroll
                for (int mi = 0; mi < 2; ++mi) {
                    #pragma unroll
                    for (int h = 0; h < 2; ++h) {
                        float* d = acc[mi][nip * 2 + h];
                        MMA_F16(d, ahf[mi], bf[2*h], bf[2*h+1]);
                        if (NA == 2) MMA_F16(d, alf[mi], bf[2*h], bf[2*h+1]);
                    }
                }
            }
        }

        CP_WAIT0();
        __syncthreads();
    }

    // epilogue via smem transpose
    float* ep = (float*)smem;
    const int r4 = lane >> 2;
    const int c2 = (lane & 3) * 2;
    #pragma unroll
    for (int mi = 0; mi < 2; ++mi) {
        #pragma unroll
        for (int ni = 0; ni < 8; ++ni) {
            int m = warp_m * 32 + mi * 16 + r4;
            int n = warp_n * 64 + ni * 8 + c2;
            ep[n * EP_STRIDE + m]           = acc[mi][ni][0];
            ep[(n + 1) * EP_STRIDE + m]     = acc[mi][ni][1];
            ep[n * EP_STRIDE + m + 8]       = acc[mi][ni][2];
            ep[(n + 1) * EP_STRIDE + m + 8] = acc[mi][ni][3];
        }
    }
    __syncthreads();

    #pragma unroll 4
    for (int it = 0; it < 64; ++it) {
        int flat = it * 256 + tid;
        int nl = flat >> 7;
        int m  = flat & 127;
        int g  = blockIdx.x * BM + m;
        int be = g / HW;
        int hwe = g - be * HW;
        int n  = n0 + nl;
        float v = ep[nl * EP_STRIDE + m] + bias[n];
        size_t idx = ((size_t)be * Mout + n) * HW + hwe;
        if (OM == OUT_RAW)            out[idx] = v;
        else if (OM == OUT_GELU)      out[idx] = gelu_f(v);
        else if (OM == OUT_GELU_ACC)  out[idx] += gelu_f(v);
        else if (OM == OUT_ADD_RES)   out[idx] = v + res[idx];
        else                          o2h[idx] = __float2half_rn(gelu_f(v));
    }
}

// ---------------- launch ----------------
extern "C" void kernel_launch(void* const* d_in, const int* in_sizes, int n_in,
                              void* d_out, int out_size)
{
    const float* x      = (const float*)d_in[0];
    const float* n1_w   = (const float*)d_in[1];
    const float* n1_b   = (const float*)d_in[2];
    const float* c1_w   = (const float*)d_in[3];
    const float* c1_b   = (const float*)d_in[4];
    const float* asn1_w = (const float*)d_in[5];
    const float* asn1_b = (const float*)d_in[6];
    const float* c21_w  = (const float*)d_in[7];
    const float* c21_b  = (const float*)d_in[8];
    const float* c22_w  = (const float*)d_in[9];
    const float* c22_b  = (const float*)d_in[10];
    const float* asn2_w = (const float*)d_in[11];
    const float* asn2_b = (const float*)d_in[12];
    const float* c3_w   = (const float*)d_in[13];
    const float* c3_b   = (const float*)d_in[14];
    const float* n2_w   = (const float*)d_in[15];
    const float* n2_b   = (const float*)d_in[16];
    const float* fc1_w  = (const float*)d_in[17];
    const float* fc1_b  = (const float*)d_in[18];
    const float* fc2_w  = (const float*)d_in[19];
    const float* fc2_b  = (const float*)d_in[20];
    float* out = (float*)d_out;

    float *bufA, *bufS, *bufX1;
    __half *pAh, *pAl, *lrh, *lrl, *tdh, *tdl, *hidh, *wh;
    float2 *part, *stats;
    cudaGetSymbolAddress((void**)&bufA,  g_bufA);
    cudaGetSymbolAddress((void**)&bufS,  g_bufS);
    cudaGetSymbolAddress((void**)&bufX1, g_bufX1);
    cudaGetSymbolAddress((void**)&pAh,   g_pAh);
    cudaGetSymbolAddress((void**)&pAl,   g_pAl);
    cudaGetSymbolAddress((void**)&lrh,   g_lrh);
    cudaGetSymbolAddress((void**)&lrl,   g_lrl);
    cudaGetSymbolAddress((void**)&tdh,   g_tdh);
    cudaGetSymbolAddress((void**)&tdl,   g_tdl);
    cudaGetSymbolAddress((void**)&hidh,  g_hidh);
    cudaGetSymbolAddress((void**)&part,  g_part);
    cudaGetSymbolAddress((void**)&stats, g_stats);
    cudaGetSymbolAddress((void**)&wh,    g_wh);

    float2* st0 = stats + 0 * B_IMG;
    float2* st1 = stats + 1 * B_IMG;
    float2* st2 = stats + 2 * B_IMG;
    float2* st3 = stats + 3 * B_IMG;

    const int NWS = C_CH * C_CH, NWB = HID_CH * C_CH;
    const int O_C1 = 0, O_C21 = NWS, O_C22 = 2*NWS, O_C3 = 3*NWS,
              O_FC1 = 4*NWS, O_FC2 = 4*NWS + NWB;

    cudaFuncSetAttribute(gemm_k<OUT_RAW, 2>,        cudaFuncAttributeMaxDynamicSharedMemorySize, SMEM_BYTES);
    cudaFuncSetAttribute(gemm_k<OUT_GELU, 2>,       cudaFuncAttributeMaxDynamicSharedMemorySize, SMEM_BYTES);
    cudaFuncSetAttribute(gemm_k<OUT_GELU_ACC, 2>,   cudaFuncAttributeMaxDynamicSharedMemorySize, SMEM_BYTES);
    cudaFuncSetAttribute(gemm_k<OUT_ADD_RES, 2>,    cudaFuncAttributeMaxDynamicSharedMemorySize, SMEM_BYTES);
    cudaFuncSetAttribute(gemm_k<OUT_GELU_PACKH, 1>, cudaFuncAttributeMaxDynamicSharedMemorySize, SMEM_BYTES);
    cudaFuncSetAttribute(gemm_k<OUT_ADD_RES, 1>,    cudaFuncAttributeMaxDynamicSharedMemorySize, SMEM_BYTES);

    dim3 redGrid(B_IMG, NBLK_RED);
    dim3 g256 (NPIX / BM, C_CH  / BN);   // (392, 2)
    dim3 g1024(NPIX / BM, HID_CH / BN);  // (392, 8)
    const int PK_BLKS = NELEM / 4 / 256;
    const int SH_BLKS = NELEM / 256;

    // #1-#3, then #4 = c1 GEMM (ncu profiles launch 4)
    reduce_part_k<<<redGrid, 256>>>(x, part);
    finalize_k<<<1, 32>>>(part, st0);
    combo_pack_wconv_k<<<dim3(PK_BLKS, 2), 256>>>(x, st0, n1_w, n1_b, pAh, pAl,
                                                  c1_w, c21_w, c22_w, c3_w, fc1_w, fc2_w, wh);
    gemm_k<OUT_RAW, 2><<<g256, 256, SMEM_BYTES>>>(
        pAh, pAl, wh + O_C1, c1_b, nullptr, bufA, nullptr, C_CH, C_CH);

    reduce_part_k<<<redGrid, 256>>>(bufA, part);
    finalize_k<<<1, 32>>>(part, st1);
    pack_shift_k<<<SH_BLKS, 256>>>(bufA, st1, asn1_w, asn1_b, lrh, lrl, tdh, tdl);
    gemm_k<OUT_GELU, 2><<<g256, 256, SMEM_BYTES>>>(
        lrh, lrl, wh + O_C21, c21_b, nullptr, bufS, nullptr, C_CH, C_CH);
    gemm_k<OUT_GELU_ACC, 2><<<g256, 256, SMEM_BYTES>>>(
        tdh, tdl, wh + O_C22, c22_b, nullptr, bufS, nullptr, C_CH, C_CH);

    reduce_part_k<<<redGrid, 256>>>(bufS, part);
    finalize_k<<<1, 32>>>(part, st2);
    pack_gn_k<<<PK_BLKS, 256>>>(bufS, st2, asn2_w, asn2_b, pAh, pAl);
    gemm_k<OUT_ADD_RES, 2><<<g256, 256, SMEM_BYTES>>>(
        pAh, pAl, wh + O_C3, c3_b, x, bufX1, nullptr, C_CH, C_CH);

    reduce_part_k<<<redGrid, 256>>>(bufX1, part);
    finalize_k<<<1, 32>>>(part, st3);
    pack_gn_k<<<PK_BLKS, 256>>>(bufX1, st3, n2_w, n2_b, pAh, pAl);
    gemm_k<OUT_GELU_PACKH, 1><<<g1024, 256, SMEM_BYTES>>>(
        pAh, nullptr, wh + O_FC1, fc1_b, nullptr, nullptr, hidh, HID_CH, C_CH);
    gemm_k<OUT_ADD_RES, 1><<<g256, 256, SMEM_BYTES>>>(
        hidh, nullptr, wh + O_FC2, fc2_b, bufX1, out, nullptr, C_CH, HID_CH);
}